// round 7
// baseline (speedup 1.0000x reference)
#include <cuda_runtime.h>
#include <cuda_bf16.h>
#include <cstdint>
#include <math.h>

#define VV 2048
#define LP1 33
#define SEQ_OFF   0
#define PROBS_OFF (512*33)
#define LOGP_OFF  (PROBS_OFF + 512*33*2048)
#define ENT_OFF   (LOGP_OFF + 512*33)

// 6-product split schedule: segment s uses A-plane PI[s], B-plane PJ[s]
// pairs: (0,0) (0,1) (1,0) (0,2) (2,0) (1,1)  == hh hm mh hl lh mm
// PI = {0,0,1,0,2,1}  PJ = {0,1,0,2,0,1}

// ---------------------------------------------------------------------------
// Persistent device scratch (no runtime allocations allowed)
// ---------------------------------------------------------------------------
__device__ __nv_bfloat16 g_Wg[2048 * 6144];  // gates weights, [new_n][k'=6*1024]
__device__ __nv_bfloat16 g_Wo[2048 * 3072];  // out_w,        [n][k'=6*512]
__device__ __nv_bfloat16 g_E6[2048 * 3072];  // embedding,    [v][6*512] (PI order)
__device__ __nv_bfloat16 g_Ag[512 * 6144];   // gates A: seg p = [e_PI[p] | h_PI[p]]
__device__ __nv_bfloat16 g_Al[512 * 3072];   // logits A: seg p = h_PI[p]
__device__ float g_part[2][512 * 2048];      // split-K partials (shared gates/logits)
__device__ float g_gum[512 * 2048];          // per-step Gumbel field
__device__ float g_c  [512 * 512];
__device__ float g_h0f[512 * 512];

// ---------------------------------------------------------------------------
__device__ __forceinline__ uint32_t smem_to_u32(const void* p) {
  uint32_t a;
  asm("{ .reg .u64 t; cvta.to.shared.u64 t, %1; cvt.u32.u64 %0, t; }"
      : "=r"(a) : "l"(p));
  return a;
}

__device__ __forceinline__ void split3(float f, __nv_bfloat16& b0,
                                       __nv_bfloat16& b1, __nv_bfloat16& b2) {
  b0 = __float2bfloat16(f);
  float r1 = f - __bfloat162float(b0);
  b1 = __float2bfloat16(r1);
  float r2 = r1 - __bfloat162float(b1);
  b2 = __float2bfloat16(r2);
}

// Threefry2x32 (exact JAX constants) — device version
__device__ __forceinline__ void tf2x32(uint32_t k0, uint32_t k1,
                                       uint32_t x0, uint32_t x1,
                                       uint32_t& o0, uint32_t& o1) {
  uint32_t ks2 = k0 ^ k1 ^ 0x1BD11BDAu;
#define TF_ROT(x,r) (((x) << (r)) | ((x) >> (32 - (r))))
#define TF_RND(r) { x0 += x1; x1 = TF_ROT(x1, r); x1 ^= x0; }
  x0 += k0; x1 += k1;
  TF_RND(13) TF_RND(15) TF_RND(26) TF_RND(6)   x0 += k1;  x1 += ks2 + 1u;
  TF_RND(17) TF_RND(29) TF_RND(16) TF_RND(24)  x0 += ks2; x1 += k0 + 2u;
  TF_RND(13) TF_RND(15) TF_RND(26) TF_RND(6)   x0 += k0;  x1 += k1 + 3u;
  TF_RND(17) TF_RND(29) TF_RND(16) TF_RND(24)  x0 += k1;  x1 += ks2 + 4u;
  TF_RND(13) TF_RND(15) TF_RND(26) TF_RND(6)   x0 += ks2; x1 += k0 + 5u;
  o0 = x0; o1 = x1;
#undef TF_RND
#undef TF_ROT
}

// host version (for per-step subkey computation)
static void h_tf2x32(uint32_t k0, uint32_t k1, uint32_t x0, uint32_t x1,
                     uint32_t& o0, uint32_t& o1) {
  uint32_t ks2 = k0 ^ k1 ^ 0x1BD11BDAu;
#define TF_ROT(x,r) (((x) << (r)) | ((x) >> (32 - (r))))
#define TF_RND(r) { x0 += x1; x1 = TF_ROT(x1, r); x1 ^= x0; }
  x0 += k0; x1 += k1;
  TF_RND(13) TF_RND(15) TF_RND(26) TF_RND(6)   x0 += k1;  x1 += ks2 + 1u;
  TF_RND(17) TF_RND(29) TF_RND(16) TF_RND(24)  x0 += ks2; x1 += k0 + 2u;
  TF_RND(13) TF_RND(15) TF_RND(26) TF_RND(6)   x0 += k0;  x1 += k1 + 3u;
  TF_RND(17) TF_RND(29) TF_RND(16) TF_RND(24)  x0 += k1;  x1 += ks2 + 4u;
  TF_RND(13) TF_RND(15) TF_RND(26) TF_RND(6)   x0 += ks2; x1 += k0 + 5u;
  o0 = x0; o1 = x1;
#undef TF_RND
#undef TF_ROT
}

__device__ __forceinline__ float sigf(float x) { return 1.0f / (1.0f + expf(-x)); }

// ---------------------------------------------------------------------------
// Setup kernels (run each replay; cheap)
// ---------------------------------------------------------------------------
__global__ __launch_bounds__(256) void k_split_wg(const float* __restrict__ w_ih,
                                                  const float* __restrict__ w_hh) {
  __shared__ float t[32][33];
  const int nt = blockIdx.x, kt = blockIdx.y;     // nt<64, kt<32
  const int tx = threadIdx.x & 31, ty = threadIdx.x >> 5;
  const int gate = nt & 3;
  const int orig = gate * 512 + ((nt >> 2) << 5) + tx;
#pragma unroll
  for (int r = 0; r < 4; r++) {
    int kl = ty + r * 8;
    int k = kt * 32 + kl;
    t[kl][tx] = (k < 512) ? w_ih[(size_t)k * 2048 + orig]
                          : w_hh[(size_t)(k - 512) * 2048 + orig];
  }
  __syncthreads();
#pragma unroll
  for (int r = 0; r < 4; r++) {
    int nl = ty + r * 8;
    float f = t[tx][nl];
    __nv_bfloat16 b0, b1, b2; split3(f, b0, b1, b2);
    size_t base = (size_t)(nt * 32 + nl) * 6144 + kt * 32 + tx;
    g_Wg[base + 0 * 1024] = b0;
    g_Wg[base + 2 * 1024] = b0;
    g_Wg[base + 4 * 1024] = b0;
    g_Wg[base + 1 * 1024] = b1;
    g_Wg[base + 5 * 1024] = b1;
    g_Wg[base + 3 * 1024] = b2;
  }
}

__global__ __launch_bounds__(256) void k_split_wo(const float* __restrict__ ow) {
  __shared__ float t[32][33];
  const int nt = blockIdx.x, kt = blockIdx.y;     // nt<64, kt<16
  const int tx = threadIdx.x & 31, ty = threadIdx.x >> 5;
#pragma unroll
  for (int r = 0; r < 4; r++) {
    int kl = ty + r * 8;
    t[kl][tx] = ow[(size_t)(kt * 32 + kl) * 2048 + nt * 32 + tx];
  }
  __syncthreads();
#pragma unroll
  for (int r = 0; r < 4; r++) {
    int nl = ty + r * 8;
    float f = t[tx][nl];
    __nv_bfloat16 b0, b1, b2; split3(f, b0, b1, b2);
    size_t base = (size_t)(nt * 32 + nl) * 3072 + kt * 32 + tx;
    g_Wo[base + 0 * 512] = b0;
    g_Wo[base + 2 * 512] = b0;
    g_Wo[base + 4 * 512] = b0;
    g_Wo[base + 1 * 512] = b1;
    g_Wo[base + 5 * 512] = b1;
    g_Wo[base + 3 * 512] = b2;
  }
}

__global__ __launch_bounds__(256) void k_split_emb(const float* __restrict__ emb) {
  int idx = blockIdx.x * 256 + threadIdx.x;       // 2048*512
  int v = idx >> 9, c = idx & 511;
  __nv_bfloat16 b0, b1, b2; split3(emb[idx], b0, b1, b2);
  size_t base = (size_t)v * 3072 + c;
  g_E6[base + 0 * 512] = b0;
  g_E6[base + 1 * 512] = b0;
  g_E6[base + 3 * 512] = b0;
  g_E6[base + 2 * 512] = b1;
  g_E6[base + 5 * 512] = b1;
  g_E6[base + 4 * 512] = b2;
}

__global__ __launch_bounds__(256) void k_splitH0() {
  int idx = blockIdx.x * 256 + threadIdx.x;       // 512*512
  int r = idx >> 9, c = idx & 511;
  __nv_bfloat16 b0, b1, b2; split3(g_h0f[idx], b0, b1, b2);
  size_t base = (size_t)r * 6144 + 512 + c;
  g_Ag[base + 0 * 1024] = b0;
  g_Ag[base + 1 * 1024] = b0;
  g_Ag[base + 3 * 1024] = b0;
  g_Ag[base + 2 * 1024] = b1;
  g_Ag[base + 5 * 1024] = b1;
  g_Ag[base + 4 * 1024] = b2;
}

__global__ __launch_bounds__(256) void k_init(const float* __restrict__ sos,
                                              float* __restrict__ out) {
  int idx = blockIdx.x * 256 + threadIdx.x;       // 512*2048
  int b = idx >> 11, v = idx & 2047;
  out[(size_t)PROBS_OFF + ((size_t)b * LP1 + 32) * VV + v] = 1.0f;
  if (v < 512) {
    __nv_bfloat16 b0, b1, b2; split3(sos[v], b0, b1, b2);
    size_t base = (size_t)b * 6144 + v;
    g_Ag[base + 0 * 1024] = b0;
    g_Ag[base + 1 * 1024] = b0;
    g_Ag[base + 3 * 1024] = b0;
    g_Ag[base + 2 * 1024] = b1;
    g_Ag[base + 5 * 1024] = b1;
    g_Ag[base + 4 * 1024] = b2;
    g_c[b * 512 + v] = 0.0f;
  }
  if (v == 0) {
    out[SEQ_OFF  + b * LP1 + 32] = 0.0f;
    out[LOGP_OFF + b * LP1 + 32] = 0.0f;
    out[ENT_OFF  + b * LP1 + 32] = 0.0f;
  }
}

// ---------------------------------------------------------------------------
// SIMT fp32 GEMM for h0 (once): h0 = x @ agent_w + agent_b
// ---------------------------------------------------------------------------
__global__ __launch_bounds__(256) void k_h0(const float* __restrict__ A,
                                            const float* __restrict__ W,
                                            const float* __restrict__ bias) {
  const int N = 512, K = 1024;
  __shared__ float As[64][17];
  __shared__ float Ws[16][64];
  const int tid = threadIdx.x;
  const int tx = tid & 15, ty = tid >> 4;
  const int m0 = blockIdx.y * 64, n0 = blockIdx.x * 64;
  float acc[4][4];
#pragma unroll
  for (int r = 0; r < 4; r++)
#pragma unroll
    for (int c = 0; c < 4; c++) acc[r][c] = 0.f;
  for (int kb = 0; kb < K; kb += 16) {
#pragma unroll
    for (int i = 0; i < 4; i++) {
      int idx = tid + i * 256;
      As[idx >> 4][idx & 15] = A[(size_t)(m0 + (idx >> 4)) * K + kb + (idx & 15)];
    }
#pragma unroll
    for (int i = 0; i < 4; i++) {
      int idx = tid + i * 256;
      Ws[idx >> 6][idx & 63] = W[(size_t)(kb + (idx >> 6)) * N + n0 + (idx & 63)];
    }
    __syncthreads();
#pragma unroll
    for (int k = 0; k < 16; k++) {
      float a[4], w[4];
#pragma unroll
      for (int r = 0; r < 4; r++) a[r] = As[ty * 4 + r][k];
#pragma unroll
      for (int c = 0; c < 4; c++) w[c] = Ws[k][tx * 4 + c];
#pragma unroll
      for (int r = 0; r < 4; r++)
#pragma unroll
        for (int c = 0; c < 4; c++) acc[r][c] = fmaf(a[r], w[c], acc[r][c]);
    }
    __syncthreads();
  }
#pragma unroll
  for (int r = 0; r < 4; r++)
#pragma unroll
    for (int c = 0; c < 4; c++)
      g_h0f[(size_t)(m0 + ty * 4 + r) * N + n0 + tx * 4 + c] =
          acc[r][c] + bias[n0 + tx * 4 + c];
}

// ---------------------------------------------------------------------------
// bf16 HMMA GEMM, 128x128 tile, BK=32, 4-stage cp.async pipeline, plus
// 4 warp-specialized Gumbel warps (threads 256..383) hashing the step's
// threefry field on the ALU pipe while tensor warps run MMA.
// Tensor group syncs on named barrier 1 (256 threads); Gumbel group never
// syncs. MODE 0: gates (KF=6144, gumbel e<32); 1: logits (3072, e>=32).
// ---------------------------------------------------------------------------
#define LDM_X4(r0,r1,r2,r3,addr) \
  asm volatile("ldmatrix.sync.aligned.m8n8.x4.shared.b16 {%0,%1,%2,%3}, [%4];" \
               : "=r"(r0), "=r"(r1), "=r"(r2), "=r"(r3) : "r"(addr))
#define MMA16816(c0,c1,c2,c3,a0,a1,a2,a3,b0,b1) \
  asm volatile("mma.sync.aligned.m16n8k16.row.col.f32.bf16.bf16.f32 " \
               "{%0,%1,%2,%3}, {%4,%5,%6,%7}, {%8,%9}, {%0,%1,%2,%3};" \
               : "+f"(c0), "+f"(c1), "+f"(c2), "+f"(c3) \
               : "r"(a0), "r"(a1), "r"(a2), "r"(a3), "r"(b0), "r"(b1))
#define BAR256() asm volatile("bar.sync 1, 256;" ::: "memory")

#define SMEM_G (4 * 20480)

template<int MODE>
__global__ __launch_bounds__(384) void k_gemm(uint32_t sk0, uint32_t sk1) {
  constexpr int KF = MODE ? 3072 : 6144;
  constexpr int KT = KF / 64;            // k-tiles (BK=32) per split-K half
  const int tid = threadIdx.x;

  if (tid >= 256) {
    // ---- Gumbel group: 128 threads x 128 CTAs = 16384 lanes, 32 elems each
    int flat = blockIdx.x + (blockIdx.y << 4) + (blockIdx.z << 6);
    int gid = flat * 128 + (tid - 256);
    const int e0 = MODE ? 32 : 0;
#pragma unroll 4
    for (int e = e0; e < e0 + 32; e++) {
      uint32_t idx = (uint32_t)(e * 16384 + gid);
      uint32_t o0, o1;
      tf2x32(sk0, sk1, 0u, idx, o0, o1);
      uint32_t bits = o0 ^ o1;
      float f = __uint_as_float((bits >> 9) | 0x3f800000u) - 1.0f;
      float u = fmaxf(f, 1.1754943508222875e-38f);
      g_gum[idx] = -logf(-logf(u));
    }
    return;
  }

  extern __shared__ __nv_bfloat16 sm[];
  const uint32_t sbase = smem_to_u32(sm);
  const __nv_bfloat16* __restrict__ A  = MODE ? g_Al : g_Ag;
  const __nv_bfloat16* __restrict__ Bt = MODE ? g_Wo : g_Wg;

  const int l = tid & 31, w = tid >> 5;
  const int wm = (w & 1) * 64, wn = (w >> 1) * 32;
  const int m0 = blockIdx.y * 128, n0 = blockIdx.x * 128;
  const int kbase = blockIdx.z * (KF / 2);
  float* __restrict__ out = &g_part[blockIdx.z][0];

  float acc[4][4][4];
#pragma unroll
  for (int a = 0; a < 4; a++)
#pragma unroll
    for (int b = 0; b < 4; b++)
#pragma unroll
      for (int c = 0; c < 4; c++) acc[a][b][c] = 0.f;

  const int lr = tid >> 2, lc = (tid & 3) * 8;

#define LOAD_STAGE(st, kt) do {                                               \
    int kk_ = kbase + (kt) * 32;                                              \
    _Pragma("unroll")                                                         \
    for (int i_ = 0; i_ < 2; i_++) {                                          \
      int r_ = lr + i_ * 64;                                                  \
      uint32_t da_ = sbase + (st) * 20480 + (r_ * 40 + lc) * 2;               \
      const __nv_bfloat16* ga_ = A + (size_t)(m0 + r_) * KF + kk_ + lc;       \
      asm volatile("cp.async.cg.shared.global [%0], [%1], 16;"                \
                   :: "r"(da_), "l"(ga_));                                    \
      uint32_t db_ = da_ + 10240;                                             \
      const __nv_bfloat16* gb_ = Bt + (size_t)(n0 + r_) * KF + kk_ + lc;      \
      asm volatile("cp.async.cg.shared.global [%0], [%1], 16;"                \
                   :: "r"(db_), "l"(gb_));                                    \
    }                                                                         \
    asm volatile("cp.async.commit_group;");                                   \
  } while (0)

  LOAD_STAGE(0, 0);
  LOAD_STAGE(1, 1);
  LOAD_STAGE(2, 2);

  for (int kt = 0; kt < KT; kt++) {
    // wait until stage kt's group is complete (own copies), then barrier
    if (kt + 2 < KT)      asm volatile("cp.async.wait_group 2;");
    else if (kt + 1 < KT) asm volatile("cp.async.wait_group 1;");
    else                  asm volatile("cp.async.wait_group 0;");
    BAR256();  // all threads' stage-kt data visible; compute(kt-1) done
    if (kt + 3 < KT) LOAD_STAGE((kt + 3) & 3, kt + 3);  // slot (kt-1)&3, free

    const uint32_t abase = sbase + (kt & 3) * 20480;
    const uint32_t bbase = abase + 10240;
#pragma unroll
    for (int kk = 0; kk < 32; kk += 16) {
      uint32_t af[4][4];
#pragma unroll
      for (int fm = 0; fm < 4; fm++) {
        int row = wm + fm * 16 + (l & 15);
        int col = kk + (l >> 4) * 8;
        LDM_X4(af[fm][0], af[fm][1], af[fm][2], af[fm][3],
               abase + (row * 40 + col) * 2);
      }
      uint32_t bf[2][4];
#pragma unroll
      for (int f2 = 0; f2 < 2; f2++) {
        int row = wn + f2 * 16 + ((l >> 4) << 3) + (l & 7);
        int col = kk + ((l >> 3) & 1) * 8;
        LDM_X4(bf[f2][0], bf[f2][1], bf[f2][2], bf[f2][3],
               bbase + (row * 40 + col) * 2);
      }
#pragma unroll
      for (int fm = 0; fm < 4; fm++)
#pragma unroll
        for (int fn = 0; fn < 4; fn++) {
          uint32_t b0 = bf[fn >> 1][(fn & 1) * 2];
          uint32_t b1 = bf[fn >> 1][(fn & 1) * 2 + 1];
          MMA16816(acc[fm][fn][0], acc[fm][fn][1], acc[fm][fn][2], acc[fm][fn][3],
                   af[fm][0], af[fm][1], af[fm][2], af[fm][3], b0, b1);
        }
    }
  }
#undef LOAD_STAGE

#pragma unroll
  for (int fm = 0; fm < 4; fm++)
#pragma unroll
    for (int fn = 0; fn < 4; fn++) {
      int r = m0 + wm + fm * 16 + (l >> 2);
      int c = n0 + wn + fn * 8 + (l & 3) * 2;
      float2 v0 = make_float2(acc[fm][fn][0], acc[fm][fn][1]);
      float2 v1 = make_float2(acc[fm][fn][2], acc[fm][fn][3]);
      *(float2*)&out[(size_t)r * 2048 + c] = v0;
      *(float2*)&out[(size_t)(r + 8) * 2048 + c] = v1;
    }
}

// ---------------------------------------------------------------------------
// LSTM pointwise: combine split-K partials, update c, write h planes.
// ---------------------------------------------------------------------------
__global__ __launch_bounds__(512) void k_lstm(const float* __restrict__ b_ih,
                                              const float* __restrict__ b_hh) {
  const int b = blockIdx.x, h = threadIdx.x;
  const int hg = h >> 5, hl = h & 31;
  float gate[4];
#pragma unroll
  for (int g = 0; g < 4; g++) {
    int nn = hg * 128 + g * 32 + hl;
    gate[g] = g_part[0][(size_t)b * 2048 + nn] + g_part[1][(size_t)b * 2048 + nn]
            + b_ih[g * 512 + h] + b_hh[g * 512 + h];
  }
  float cv = g_c[b * 512 + h];
  float cn = sigf(gate[1]) * cv + sigf(gate[0]) * tanhf(gate[2]);
  float hn = sigf(gate[3]) * tanhf(cn);
  g_c[b * 512 + h] = cn;
  __nv_bfloat16 p0, p1, p2; split3(hn, p0, p1, p2);
  __nv_bfloat16 pl[3] = {p0, p1, p2};
  const int PI[6] = {0, 0, 1, 0, 2, 1};
#pragma unroll
  for (int s = 0; s < 6; s++) {
    g_Ag[(size_t)b * 6144 + s * 1024 + 512 + h] = pl[PI[s]];
    g_Al[(size_t)b * 3072 + s * 512 + h]        = pl[PI[s]];
  }
}

// ---------------------------------------------------------------------------
// Sampler: combine logits partials + bias, log-softmax, probs/entropy,
// Gumbel-argmax using precomputed g_gum, embedding gather.
// ---------------------------------------------------------------------------
__global__ __launch_bounds__(256) void k_sample(const float* __restrict__ ob,
                                                float* __restrict__ out, int t) {
  const int b = blockIdx.x;
  const int tid = threadIdx.x;
  const float* __restrict__ p0 = &g_part[0][(size_t)b * VV];
  const float* __restrict__ p1 = &g_part[1][(size_t)b * VV];
  const float* __restrict__ gum = &g_gum[(size_t)b * VV];

  float zv[8];
#pragma unroll
  for (int j = 0; j < 8; j++) {
    int v = tid + j * 256;
    zv[j] = p0[v] + p1[v] + ob[v];
  }

  __shared__ float red[256];
  __shared__ float rv[256];
  __shared__ int   ri[256];
  __shared__ int   s_sym;

  float m = zv[0];
#pragma unroll
  for (int j = 1; j < 8; j++) m = fmaxf(m, zv[j]);
  red[tid] = m; __syncthreads();
  for (int s = 128; s > 0; s >>= 1) {
    if (tid < s) red[tid] = fmaxf(red[tid], red[tid + s]);
    __syncthreads();
  }
  const float M = red[0]; __syncthreads();

  float ssum = 0.f;
#pragma unroll
  for (int j = 0; j < 8; j++) ssum += __expf(zv[j] - M);
  red[tid] = ssum; __syncthreads();
  for (int s = 128; s > 0; s >>= 1) {
    if (tid < s) red[tid] += red[tid + s];
    __syncthreads();
  }
  const float lse = logf(red[0]); __syncthreads();

  float entp = 0.f;
  float bestv = -INFINITY;
  int   besti = VV;
  const size_t probs_row = (size_t)PROBS_OFF + ((size_t)b * LP1 + t) * VV;
#pragma unroll
  for (int j = 0; j < 8; j++) {
    int v = tid + j * 256;
    float lsm = zv[j] - M - lse;
    float pr = __expf(lsm);
    out[probs_row + v] = pr;
    entp += pr * lsm;
    float val = gum[v] + lsm;
    if (val > bestv || (val == bestv && v < besti)) { bestv = val; besti = v; }
  }

  red[tid] = entp; __syncthreads();
  for (int s = 128; s > 0; s >>= 1) {
    if (tid < s) red[tid] += red[tid + s];
    __syncthreads();
  }
  const float ENT = red[0]; __syncthreads();

  rv[tid] = bestv; ri[tid] = besti; __syncthreads();
  for (int s = 128; s > 0; s >>= 1) {
    if (tid < s) {
      if (rv[tid + s] > rv[tid] ||
          (rv[tid + s] == rv[tid] && ri[tid + s] < ri[tid])) {
        rv[tid] = rv[tid + s]; ri[tid] = ri[tid + s];
      }
    }
    __syncthreads();
  }
  if (tid == 0) {
    int sym = ri[0];
    s_sym = sym;
    out[SEQ_OFF  + b * LP1 + t] = (float)sym;
    out[LOGP_OFF + b * LP1 + t] = (p0[sym] + p1[sym] + ob[sym]) - M - lse;
    out[ENT_OFF  + b * LP1 + t] = -ENT;
  }
  __syncthreads();
  const int sym = s_sym;
  const uint32_t* src = (const uint32_t*)&g_E6[(size_t)sym * 3072];
  uint32_t* dst = (uint32_t*)&g_Ag[(size_t)b * 6144];
#pragma unroll
  for (int s = 0; s < 6; s++)
    dst[s * 512 + tid] = src[s * 256 + tid];
}

// ---------------------------------------------------------------------------
extern "C" void kernel_launch(void* const* d_in, const int* in_sizes, int n_in,
                              void* d_out, int out_size) {
  const float* x       = (const float*)d_in[0];
  const float* agent_w = (const float*)d_in[1];
  const float* agent_b = (const float*)d_in[2];
  const float* sos     = (const float*)d_in[3];
  const float* emb     = (const float*)d_in[4];
  const float* w_ih    = (const float*)d_in[5];
  const float* w_hh    = (const float*)d_in[6];
  const float* b_ih    = (const float*)d_in[7];
  const float* b_hh    = (const float*)d_in[8];
  const float* out_w   = (const float*)d_in[9];
  const float* out_b   = (const float*)d_in[10];
  float* out = (float*)d_out;

  cudaFuncSetAttribute(k_gemm<0>, cudaFuncAttributeMaxDynamicSharedMemorySize, SMEM_G);
  cudaFuncSetAttribute(k_gemm<1>, cudaFuncAttributeMaxDynamicSharedMemorySize, SMEM_G);

  // per-step threefry subkeys (key chain depends only on t)
  uint32_t sk0[32], sk1[32];
  {
    uint32_t k0 = 0u, k1 = 1u;
    for (int t = 0; t < 32; t++) {
      uint32_t n0, n1, s0, s1;
      h_tf2x32(k0, k1, 0u, 0u, n0, n1);
      h_tf2x32(k0, k1, 0u, 1u, s0, s1);
      sk0[t] = s0; sk1[t] = s1; k0 = n0; k1 = n1;
    }
  }

  k_init<<<4096, 256>>>(sos, out);
  k_split_emb<<<4096, 256>>>(emb);
  k_split_wg<<<dim3(64, 32), 256>>>(w_ih, w_hh);
  k_split_wo<<<dim3(64, 16), 256>>>(out_w);
  k_h0<<<dim3(8, 8), 256>>>(x, agent_w, agent_b);
  k_splitH0<<<1024, 256>>>();

  for (int t = 0; t < 32; t++) {
    k_gemm<0><<<dim3(16, 4, 2), 384, SMEM_G>>>(sk0[t], sk1[t]);
    k_lstm<<<512, 512>>>(b_ih, b_hh);
    k_gemm<1><<<dim3(16, 4, 2), 384, SMEM_G>>>(sk0[t], sk1[t]);
    k_sample<<<512, 256>>>(out_b, out, t);
  }
}

// round 8
// speedup vs baseline: 1.9164x; 1.9164x over previous
#include <cuda_runtime.h>
#include <cuda_bf16.h>
#include <cstdint>
#include <math.h>

#define VV 2048
#define LP1 33
#define SEQ_OFF   0
#define PROBS_OFF (512*33)
#define LOGP_OFF  (PROBS_OFF + 512*33*2048)
#define ENT_OFF   (LOGP_OFF + 512*33)

// 6-product bf16 split schedule over K'=6*512=3072:
// segment s uses A-plane PI[s], B-plane PJ[s]
// pairs: (0,0) (0,1) (1,0) (0,2) (2,0) (1,1)
// PI = {0,0,1,0,2,1} -> plane0 segs {0,1,3}, plane1 {2,5}, plane2 {4}
// PJ = {0,1,0,2,0,1} -> plane0 segs {0,2,4}, plane1 {1,5}, plane2 {3}

// ---------------------------------------------------------------------------
// Persistent device scratch (no runtime allocations allowed)
// ---------------------------------------------------------------------------
__device__ __nv_bfloat16 g_Whh[2048 * 3072];  // w_hh planes, [perm_n][3072], PJ
__device__ __nv_bfloat16 g_Wih[2048 * 3072];  // w_ih planes, [perm_n][3072], PJ
__device__ __nv_bfloat16 g_Wo [2048 * 3072];  // out_w planes, [n][3072], PJ
__device__ __nv_bfloat16 g_E6p[2176 * 3072];  // emb(+sos row 2048, zero pad) PI
__device__ __nv_bfloat16 g_Ah [512 * 3072];   // h planes, PI order
__device__ float g_EG[2176 * 2048];           // precomputed (emb|sos) @ w_ih (perm n)
__device__ float g_part[2][512 * 2048];       // split-K partials
__device__ float g_c  [512 * 512];
__device__ int   g_sym[512];

// ---------------------------------------------------------------------------
__device__ __forceinline__ uint32_t smem_to_u32(const void* p) {
  uint32_t a;
  asm("{ .reg .u64 t; cvta.to.shared.u64 t, %1; cvt.u32.u64 %0, t; }"
      : "=r"(a) : "l"(p));
  return a;
}

__device__ __forceinline__ void split3(float f, __nv_bfloat16& b0,
                                       __nv_bfloat16& b1, __nv_bfloat16& b2) {
  b0 = __float2bfloat16(f);
  float r1 = f - __bfloat162float(b0);
  b1 = __float2bfloat16(r1);
  float r2 = r1 - __bfloat162float(b1);
  b2 = __float2bfloat16(r2);
}

// Threefry2x32 (exact JAX constants)
__device__ __forceinline__ void tf2x32(uint32_t k0, uint32_t k1,
                                       uint32_t x0, uint32_t x1,
                                       uint32_t& o0, uint32_t& o1) {
  uint32_t ks2 = k0 ^ k1 ^ 0x1BD11BDAu;
#define TF_ROT(x,r) (((x) << (r)) | ((x) >> (32 - (r))))
#define TF_RND(r) { x0 += x1; x1 = TF_ROT(x1, r); x1 ^= x0; }
  x0 += k0; x1 += k1;
  TF_RND(13) TF_RND(15) TF_RND(26) TF_RND(6)   x0 += k1;  x1 += ks2 + 1u;
  TF_RND(17) TF_RND(29) TF_RND(16) TF_RND(24)  x0 += ks2; x1 += k0 + 2u;
  TF_RND(13) TF_RND(15) TF_RND(26) TF_RND(6)   x0 += k0;  x1 += k1 + 3u;
  TF_RND(17) TF_RND(29) TF_RND(16) TF_RND(24)  x0 += k1;  x1 += ks2 + 4u;
  TF_RND(13) TF_RND(15) TF_RND(26) TF_RND(6)   x0 += ks2; x1 += k0 + 5u;
  o0 = x0; o1 = x1;
#undef TF_RND
#undef TF_ROT
}

__device__ __forceinline__ float sigf(float x) { return 1.0f / (1.0f + expf(-x)); }

// ---------------------------------------------------------------------------
// Setup kernels
// ---------------------------------------------------------------------------
// w_hh / w_ih: orig [k=512][2048] -> [perm_n][3072] (PJ plane order),
// perm_n = hgroup*128 + gate*32 + hl  (orig col = gate*512 + hgroup*32 + hl)
__global__ __launch_bounds__(256) void k_split_whh(const float* __restrict__ w) {
  __shared__ float t[32][33];
  const int nt = blockIdx.x, kt = blockIdx.y;     // nt<64, kt<16
  const int tx = threadIdx.x & 31, ty = threadIdx.x >> 5;
  const int gate = nt & 3;
  const int orig = gate * 512 + ((nt >> 2) << 5) + tx;
#pragma unroll
  for (int r = 0; r < 4; r++) {
    int kl = ty + r * 8;
    t[kl][tx] = w[(size_t)(kt * 32 + kl) * 2048 + orig];
  }
  __syncthreads();
#pragma unroll
  for (int r = 0; r < 4; r++) {
    int nl = ty + r * 8;
    float f = t[tx][nl];
    __nv_bfloat16 b0, b1, b2; split3(f, b0, b1, b2);
    size_t base = (size_t)(nt * 32 + nl) * 3072 + kt * 32 + tx;
    g_Whh[base + 0 * 512] = b0;
    g_Whh[base + 2 * 512] = b0;
    g_Whh[base + 4 * 512] = b0;
    g_Whh[base + 1 * 512] = b1;
    g_Whh[base + 5 * 512] = b1;
    g_Whh[base + 3 * 512] = b2;
  }
}

__global__ __launch_bounds__(256) void k_split_wih(const float* __restrict__ w) {
  __shared__ float t[32][33];
  const int nt = blockIdx.x, kt = blockIdx.y;
  const int tx = threadIdx.x & 31, ty = threadIdx.x >> 5;
  const int gate = nt & 3;
  const int orig = gate * 512 + ((nt >> 2) << 5) + tx;
#pragma unroll
  for (int r = 0; r < 4; r++) {
    int kl = ty + r * 8;
    t[kl][tx] = w[(size_t)(kt * 32 + kl) * 2048 + orig];
  }
  __syncthreads();
#pragma unroll
  for (int r = 0; r < 4; r++) {
    int nl = ty + r * 8;
    float f = t[tx][nl];
    __nv_bfloat16 b0, b1, b2; split3(f, b0, b1, b2);
    size_t base = (size_t)(nt * 32 + nl) * 3072 + kt * 32 + tx;
    g_Wih[base + 0 * 512] = b0;
    g_Wih[base + 2 * 512] = b0;
    g_Wih[base + 4 * 512] = b0;
    g_Wih[base + 1 * 512] = b1;
    g_Wih[base + 5 * 512] = b1;
    g_Wih[base + 3 * 512] = b2;
  }
}

// out_w: [k=512][2048] -> g_Wo[n][3072] (no gate permutation)
__global__ __launch_bounds__(256) void k_split_wo(const float* __restrict__ ow) {
  __shared__ float t[32][33];
  const int nt = blockIdx.x, kt = blockIdx.y;     // nt<64, kt<16
  const int tx = threadIdx.x & 31, ty = threadIdx.x >> 5;
#pragma unroll
  for (int r = 0; r < 4; r++) {
    int kl = ty + r * 8;
    t[kl][tx] = ow[(size_t)(kt * 32 + kl) * 2048 + nt * 32 + tx];
  }
  __syncthreads();
#pragma unroll
  for (int r = 0; r < 4; r++) {
    int nl = ty + r * 8;
    float f = t[tx][nl];
    __nv_bfloat16 b0, b1, b2; split3(f, b0, b1, b2);
    size_t base = (size_t)(nt * 32 + nl) * 3072 + kt * 32 + tx;
    g_Wo[base + 0 * 512] = b0;
    g_Wo[base + 2 * 512] = b0;
    g_Wo[base + 4 * 512] = b0;
    g_Wo[base + 1 * 512] = b1;
    g_Wo[base + 5 * 512] = b1;
    g_Wo[base + 3 * 512] = b2;
  }
}

// embedding planes (PI order) rows 0..2047, sos row 2048, zero pad 2049..2175
__global__ __launch_bounds__(256) void k_split_emb(const float* __restrict__ emb,
                                                   const float* __restrict__ sos) {
  int idx = blockIdx.x * 256 + threadIdx.x;
  if (idx < 2048 * 512) {
    int v = idx >> 9, c = idx & 511;
    __nv_bfloat16 b0, b1, b2; split3(emb[idx], b0, b1, b2);
    size_t base = (size_t)v * 3072 + c;
    g_E6p[base + 0 * 512] = b0;
    g_E6p[base + 1 * 512] = b0;
    g_E6p[base + 3 * 512] = b0;
    g_E6p[base + 2 * 512] = b1;
    g_E6p[base + 5 * 512] = b1;
    g_E6p[base + 4 * 512] = b2;
  } else if (idx < 2048 * 512 + 512) {
    int c = idx - 2048 * 512;
    __nv_bfloat16 b0, b1, b2; split3(sos[c], b0, b1, b2);
    size_t base = (size_t)2048 * 3072 + c;
    g_E6p[base + 0 * 512] = b0;
    g_E6p[base + 1 * 512] = b0;
    g_E6p[base + 3 * 512] = b0;
    g_E6p[base + 2 * 512] = b1;
    g_E6p[base + 5 * 512] = b1;
    g_E6p[base + 4 * 512] = b2;
  } else if (idx < 2048 * 512 + 512 + 127 * 3072) {
    int j = idx - (2048 * 512 + 512);
    g_E6p[(size_t)2049 * 3072 + j] = __float2bfloat16(0.0f);
  }
}

__global__ __launch_bounds__(256) void k_init(float* __restrict__ out) {
  int idx = blockIdx.x * 256 + threadIdx.x;       // 512*2048
  int b = idx >> 11, v = idx & 2047;
  out[(size_t)PROBS_OFF + ((size_t)b * LP1 + 32) * VV + v] = 1.0f;
  if (v < 512) g_c[b * 512 + v] = 0.0f;
  if (v == 0) {
    g_sym[b] = 2048;   // sos row of g_EG for step 0
    out[SEQ_OFF  + b * LP1 + 32] = 0.0f;
    out[LOGP_OFF + b * LP1 + 32] = 0.0f;
    out[ENT_OFF  + b * LP1 + 32] = 0.0f;
  }
}

// ---------------------------------------------------------------------------
// SIMT fp32 GEMM for h0 (once): h0 = x @ agent_w + agent_b -> g_Ah planes
// ---------------------------------------------------------------------------
__global__ __launch_bounds__(256) void k_h0(const float* __restrict__ A,
                                            const float* __restrict__ W,
                                            const float* __restrict__ bias) {
  const int N = 512, K = 1024;
  __shared__ float As[64][17];
  __shared__ float Ws[16][64];
  const int tid = threadIdx.x;
  const int tx = tid & 15, ty = tid >> 4;
  const int m0 = blockIdx.y * 64, n0 = blockIdx.x * 64;
  float acc[4][4];
#pragma unroll
  for (int r = 0; r < 4; r++)
#pragma unroll
    for (int c = 0; c < 4; c++) acc[r][c] = 0.f;
  for (int kb = 0; kb < K; kb += 16) {
#pragma unroll
    for (int i = 0; i < 4; i++) {
      int idx = tid + i * 256;
      As[idx >> 4][idx & 15] = A[(size_t)(m0 + (idx >> 4)) * K + kb + (idx & 15)];
    }
#pragma unroll
    for (int i = 0; i < 4; i++) {
      int idx = tid + i * 256;
      Ws[idx >> 6][idx & 63] = W[(size_t)(kb + (idx >> 6)) * N + n0 + (idx & 63)];
    }
    __syncthreads();
#pragma unroll
    for (int k = 0; k < 16; k++) {
      float a[4], w[4];
#pragma unroll
      for (int r = 0; r < 4; r++) a[r] = As[ty * 4 + r][k];
#pragma unroll
      for (int c = 0; c < 4; c++) w[c] = Ws[k][tx * 4 + c];
#pragma unroll
      for (int r = 0; r < 4; r++)
#pragma unroll
        for (int c = 0; c < 4; c++) acc[r][c] = fmaf(a[r], w[c], acc[r][c]);
    }
    __syncthreads();
  }
#pragma unroll
  for (int r = 0; r < 4; r++)
#pragma unroll
    for (int c = 0; c < 4; c++) {
      int row = m0 + ty * 4 + r, col = n0 + tx * 4 + c;
      float hn = acc[r][c] + bias[col];
      __nv_bfloat16 b0, b1, b2; split3(hn, b0, b1, b2);
      size_t base = (size_t)row * 3072 + col;
      g_Ah[base + 0 * 512] = b0;
      g_Ah[base + 1 * 512] = b0;
      g_Ah[base + 3 * 512] = b0;
      g_Ah[base + 2 * 512] = b1;
      g_Ah[base + 5 * 512] = b1;
      g_Ah[base + 4 * 512] = b2;
    }
}

// ---------------------------------------------------------------------------
// bf16 HMMA GEMM, 128x128 tile, BK=32, 4-stage cp.async, single sync/iter.
// MODE 0: gates  part[z] = h  @ Whh   (grid 16,4,2; KT=48/half)
// MODE 1: logits part[z] = h  @ Wo    (grid 16,4,2; KT=48/half)
// MODE 2: EG     g_EG    = E6p @ Wih  (grid 16,17,1; KT=96)
// ---------------------------------------------------------------------------
#define LDM_X4(r0,r1,r2,r3,addr) \
  asm volatile("ldmatrix.sync.aligned.m8n8.x4.shared.b16 {%0,%1,%2,%3}, [%4];" \
               : "=r"(r0), "=r"(r1), "=r"(r2), "=r"(r3) : "r"(addr))
#define MMA16816(c0,c1,c2,c3,a0,a1,a2,a3,b0,b1) \
  asm volatile("mma.sync.aligned.m16n8k16.row.col.f32.bf16.bf16.f32 " \
               "{%0,%1,%2,%3}, {%4,%5,%6,%7}, {%8,%9}, {%0,%1,%2,%3};" \
               : "+f"(c0), "+f"(c1), "+f"(c2), "+f"(c3) \
               : "r"(a0), "r"(a1), "r"(a2), "r"(a3), "r"(b0), "r"(b1))

#define SMEM_G (4 * 20480)

template<int MODE>
__global__ __launch_bounds__(256) void k_gemm() {
  constexpr int KF = 3072;
  constexpr int KT = (MODE == 2) ? 96 : 48;
  const __nv_bfloat16* __restrict__ A  = (MODE == 2) ? g_E6p : g_Ah;
  const __nv_bfloat16* __restrict__ Bt = (MODE == 0) ? g_Whh
                                        : (MODE == 1) ? g_Wo : g_Wih;

  extern __shared__ __nv_bfloat16 sm[];
  const uint32_t sbase = smem_to_u32(sm);

  const int tid = threadIdx.x;
  const int l = tid & 31, w = tid >> 5;
  const int wm = (w & 1) * 64, wn = (w >> 1) * 32;
  const int m0 = blockIdx.y * 128, n0 = blockIdx.x * 128;
  const int kbase = (MODE == 2) ? 0 : blockIdx.z * 1536;
  float* __restrict__ out = (MODE == 2) ? g_EG : &g_part[blockIdx.z][0];

  float acc[4][4][4];
#pragma unroll
  for (int a = 0; a < 4; a++)
#pragma unroll
    for (int b = 0; b < 4; b++)
#pragma unroll
      for (int c = 0; c < 4; c++) acc[a][b][c] = 0.f;

  const int lr = tid >> 2, lc = (tid & 3) * 8;

#define LOAD_STAGE(st, kt) do {                                               \
    int kk_ = kbase + (kt) * 32;                                              \
    _Pragma("unroll")                                                         \
    for (int i_ = 0; i_ < 2; i_++) {                                          \
      int r_ = lr + i_ * 64;                                                  \
      uint32_t da_ = sbase + (st) * 20480 + (r_ * 40 + lc) * 2;               \
      const __nv_bfloat16* ga_ = A + (size_t)(m0 + r_) * KF + kk_ + lc;       \
      asm volatile("cp.async.cg.shared.global [%0], [%1], 16;"                \
                   :: "r"(da_), "l"(ga_));                                    \
      uint32_t db_ = da_ + 10240;                                             \
      const __nv_bfloat16* gb_ = Bt + (size_t)(n0 + r_) * KF + kk_ + lc;      \
      asm volatile("cp.async.cg.shared.global [%0], [%1], 16;"                \
                   :: "r"(db_), "l"(gb_));                                    \
    }                                                                         \
    asm volatile("cp.async.commit_group;");                                   \
  } while (0)

  LOAD_STAGE(0, 0);
  LOAD_STAGE(1, 1);
  LOAD_STAGE(2, 2);

  for (int kt = 0; kt < KT; kt++) {
    if (kt < KT - 2)       asm volatile("cp.async.wait_group 2;");
    else if (kt == KT - 2) asm volatile("cp.async.wait_group 1;");
    else                   asm volatile("cp.async.wait_group 0;");
    __syncthreads();   // group-kt data visible to all; compute(kt-1) done
    if (kt + 3 < KT) LOAD_STAGE((kt + 3) & 3, kt + 3);   // slot (kt-1)&3 free

    const uint32_t abase = sbase + (kt & 3) * 20480;
    const uint32_t bbase = abase + 10240;
#pragma unroll
    for (int kk = 0; kk < 32; kk += 16) {
      uint32_t af[4][4];
#pragma unroll
      for (int fm = 0; fm < 4; fm++) {
        int row = wm + fm * 16 + (l & 15);
        int col = kk + (l >> 4) * 8;
        LDM_X4(af[fm][0], af[fm][1], af[fm][2], af[fm][3],
               abase + (row * 40 + col) * 2);
      }
      uint32_t bf[2][4];
#pragma unroll
      for (int f2 = 0; f2 < 2; f2++) {
        int row = wn + f2 * 16 + ((l >> 4) << 3) + (l & 7);
        int col = kk + ((l >> 3) & 1) * 8;
        LDM_X4(bf[f2][0], bf[f2][1], bf[f2][2], bf[f2][3],
               bbase + (row * 40 + col) * 2);
      }
#pragma unroll
      for (int fm = 0; fm < 4; fm++)
#pragma unroll
        for (int fn = 0; fn < 4; fn++) {
          uint32_t b0 = bf[fn >> 1][(fn & 1) * 2];
          uint32_t b1 = bf[fn >> 1][(fn & 1) * 2 + 1];
          MMA16816(acc[fm][fn][0], acc[fm][fn][1], acc[fm][fn][2], acc[fm][fn][3],
                   af[fm][0], af[fm][1], af[fm][2], af[fm][3], b0, b1);
        }
    }
  }
#undef LOAD_STAGE

#pragma unroll
  for (int fm = 0; fm < 4; fm++)
#pragma unroll
    for (int fn = 0; fn < 4; fn++) {
      int r = m0 + wm + fm * 16 + (l >> 2);
      int c = n0 + wn + fn * 8 + (l & 3) * 2;
      float2 v0 = make_float2(acc[fm][fn][0], acc[fm][fn][1]);
      float2 v1 = make_float2(acc[fm][fn][2], acc[fm][fn][3]);
      *(float2*)&out[(size_t)r * 2048 + c] = v0;
      *(float2*)&out[(size_t)(r + 8) * 2048 + c] = v1;
    }
}

// ---------------------------------------------------------------------------
// LSTM pointwise: gates = partials + EG[sym[b]] + biases; update c; write h
// planes (PI order) into g_Ah. 512 blocks x 512 threads.
// ---------------------------------------------------------------------------
__global__ __launch_bounds__(512) void k_lstm(const float* __restrict__ b_ih,
                                              const float* __restrict__ b_hh) {
  const int b = blockIdx.x, h = threadIdx.x;
  const int hg = h >> 5, hl = h & 31;
  const int sym = g_sym[b];
  const float* __restrict__ eg = &g_EG[(size_t)sym * 2048];
  float gate[4];
#pragma unroll
  for (int g = 0; g < 4; g++) {
    int nn = hg * 128 + g * 32 + hl;
    gate[g] = g_part[0][(size_t)b * 2048 + nn] + g_part[1][(size_t)b * 2048 + nn]
            + eg[nn] + b_ih[g * 512 + h] + b_hh[g * 512 + h];
  }
  float cv = g_c[b * 512 + h];
  float cn = sigf(gate[1]) * cv + sigf(gate[0]) * tanhf(gate[2]);
  float hn = sigf(gate[3]) * tanhf(cn);
  g_c[b * 512 + h] = cn;
  __nv_bfloat16 p0, p1, p2; split3(hn, p0, p1, p2);
  size_t base = (size_t)b * 3072 + h;
  g_Ah[base + 0 * 512] = p0;
  g_Ah[base + 1 * 512] = p0;
  g_Ah[base + 3 * 512] = p0;
  g_Ah[base + 2 * 512] = p1;
  g_Ah[base + 5 * 512] = p1;
  g_Ah[base + 4 * 512] = p2;
}

// ---------------------------------------------------------------------------
// Sampler: combine logits partials + bias, log-softmax, probs/entropy,
// Gumbel-argmax (JAX partitionable threefry), record sym.
// ---------------------------------------------------------------------------
__global__ __launch_bounds__(256) void k_sample(const float* __restrict__ ob,
                                                float* __restrict__ out, int t) {
  const int b = blockIdx.x;
  const int tid = threadIdx.x;
  const float* __restrict__ p0 = &g_part[0][(size_t)b * VV];
  const float* __restrict__ p1 = &g_part[1][(size_t)b * VV];

  float zv[8];
#pragma unroll
  for (int j = 0; j < 8; j++) {
    int v = tid + j * 256;
    zv[j] = p0[v] + p1[v] + ob[v];
  }

  __shared__ float red[256];
  __shared__ float rv[256];
  __shared__ int   ri[256];
  __shared__ int   s_sym;

  float m = zv[0];
#pragma unroll
  for (int j = 1; j < 8; j++) m = fmaxf(m, zv[j]);
  red[tid] = m; __syncthreads();
  for (int s = 128; s > 0; s >>= 1) {
    if (tid < s) red[tid] = fmaxf(red[tid], red[tid + s]);
    __syncthreads();
  }
  const float M = red[0]; __syncthreads();

  float ssum = 0.f;
#pragma unroll
  for (int j = 0; j < 8; j++) ssum += __expf(zv[j] - M);
  red[tid] = ssum; __syncthreads();
  for (int s = 128; s > 0; s >>= 1) {
    if (tid < s) red[tid] += red[tid + s];
    __syncthreads();
  }
  const float lse = logf(red[0]); __syncthreads();

  // key chain: key0=(0,1); per step: new_key=tf(key,(0,0)), subkey=tf(key,(0,1))
  uint32_t k0 = 0u, k1 = 1u, sk0 = 0u, sk1 = 0u;
  for (int st = 0; st <= t; st++) {
    uint32_t n0, n1, s0, s1;
    tf2x32(k0, k1, 0u, 0u, n0, n1);
    tf2x32(k0, k1, 0u, 1u, s0, s1);
    sk0 = s0; sk1 = s1; k0 = n0; k1 = n1;
  }

  float entp = 0.f;
  float bestv = -INFINITY;
  int   besti = VV;
  const size_t probs_row = (size_t)PROBS_OFF + ((size_t)b * LP1 + t) * VV;
#pragma unroll
  for (int j = 0; j < 8; j++) {
    int v = tid + j * 256;
    float lsm = zv[j] - M - lse;
    float pr = __expf(lsm);
    out[probs_row + v] = pr;
    entp += pr * lsm;
    uint32_t o0, o1;
    tf2x32(sk0, sk1, 0u, (uint32_t)(b * VV + v), o0, o1);
    uint32_t bits = o0 ^ o1;
    float f = __uint_as_float((bits >> 9) | 0x3f800000u) - 1.0f;
    float u = fmaxf(f, 1.1754943508222875e-38f);
    float gum = -logf(-logf(u));
    float val = gum + lsm;
    if (val > bestv || (val == bestv && v < besti)) { bestv = val; besti = v; }
  }

  red[tid] = entp; __syncthreads();
  for (int s = 128; s > 0; s >>= 1) {
    if (tid < s) red[tid] += red[tid + s];
    __syncthreads();
  }
  const float ENT = red[0]; __syncthreads();

  rv[tid] = bestv; ri[tid] = besti; __syncthreads();
  for (int s = 128; s > 0; s >>= 1) {
    if (tid < s) {
      if (rv[tid + s] > rv[tid] ||
          (rv[tid + s] == rv[tid] && ri[tid + s] < ri[tid])) {
        rv[tid] = rv[tid + s]; ri[tid] = ri[tid + s];
      }
    }
    __syncthreads();
  }
  if (tid == 0) {
    int sym = ri[0];
    s_sym = sym;
    g_sym[b] = sym;
    out[SEQ_OFF  + b * LP1 + t] = (float)sym;
    out[LOGP_OFF + b * LP1 + t] = (p0[sym] + p1[sym] + ob[sym]) - M - lse;
    out[ENT_OFF  + b * LP1 + t] = -ENT;
  }
}

// ---------------------------------------------------------------------------
extern "C" void kernel_launch(void* const* d_in, const int* in_sizes, int n_in,
                              void* d_out, int out_size) {
  const float* x       = (const float*)d_in[0];
  const float* agent_w = (const float*)d_in[1];
  const float* agent_b = (const float*)d_in[2];
  const float* sos     = (const float*)d_in[3];
  const float* emb     = (const float*)d_in[4];
  const float* w_ih    = (const float*)d_in[5];
  const float* w_hh    = (const float*)d_in[6];
  const float* b_ih    = (const float*)d_in[7];
  const float* b_hh    = (const float*)d_in[8];
  const float* out_w   = (const float*)d_in[9];
  const float* out_b   = (const float*)d_in[10];
  float* out = (float*)d_out;

  cudaFuncSetAttribute(k_gemm<0>, cudaFuncAttributeMaxDynamicSharedMemorySize, SMEM_G);
  cudaFuncSetAttribute(k_gemm<1>, cudaFuncAttributeMaxDynamicSharedMemorySize, SMEM_G);
  cudaFuncSetAttribute(k_gemm<2>, cudaFuncAttributeMaxDynamicSharedMemorySize, SMEM_G);

  // 5 setup launches, then k_gemm<2> is launch #6 -> captured by ncu (-s 5 -c 1)
  k_init<<<4096, 256>>>(out);
  k_split_emb<<<5622, 256>>>(emb, sos);
  k_split_wih<<<dim3(64, 16), 256>>>(w_ih);
  k_split_whh<<<dim3(64, 16), 256>>>(w_hh);
  k_split_wo<<<dim3(64, 16), 256>>>(out_w);
  k_gemm<2><<<dim3(16, 17, 1), 256, SMEM_G>>>();   // EG precompute (profiled)
  k_h0<<<dim3(8, 8), 256>>>(x, agent_w, agent_b);

  for (int t = 0; t < 32; t++) {
    k_gemm<0><<<dim3(16, 4, 2), 256, SMEM_G>>>();  // gates = h @ Whh
    k_lstm<<<512, 512>>>(b_ih, b_hh);              // + EG[sym] + biases
    k_gemm<1><<<dim3(16, 4, 2), 256, SMEM_G>>>();  // logits = h @ Wo
    k_sample<<<512, 256>>>(out_b, out, t);
  }
}

// round 9
// speedup vs baseline: 2.1164x; 1.1043x over previous
#include <cuda_runtime.h>
#include <cuda_fp16.h>
#include <cstdint>
#include <math.h>

#define VV 2048
#define LP1 33
#define SEQ_OFF   0
#define PROBS_OFF (512*33)
#define LOGP_OFF  (PROBS_OFF + 512*33*2048)
#define ENT_OFF   (LOGP_OFF + 512*33)

// fp16 x 4-product split, K' = 4*512 = 2048.
// A segs: [a0 | a0*2^-5 | a1s | a1s*2^-12],  a1s = fp16((h-a0)*2^6)
// B segs: [b0 | b1s*2^-1 | b0*2^-6 | b1s],   b1s = fp16((w-w0)*2^6)
// seg products: a0*b0, a0*(w-w0), (h-a0)*b0, (h-a0)(w-w0)  (all true scale)

// ---------------------------------------------------------------------------
// Persistent device scratch
// ---------------------------------------------------------------------------
__device__ __half g_Whh[2048 * 2048];   // w_hh B-planes, [perm_n][2048]
__device__ __half g_Wih[2048 * 2048];   // w_ih B-planes, [perm_n][2048]
__device__ __half g_Wo [2048 * 2048];   // out_w B-planes, [n][2048]
__device__ __half g_E6p[2176 * 2048];   // emb(+sos@2048, zero pad) A-planes
__device__ __half g_Ah [2][512 * 2048]; // h A-planes, ping-pong
__device__ float g_EG[2176 * 2048];     // (emb|sos) @ w_ih, perm n, fp32
__device__ float g_z [512 * 2048];      // logits
__device__ float g_bg[2048];            // b_ih+b_hh in perm order
__device__ float g_c [512 * 512];
__device__ float g_h0f[512 * 512];
__device__ int   g_sym[512];

// ---------------------------------------------------------------------------
__device__ __forceinline__ uint32_t smem_to_u32(const void* p) {
  uint32_t a;
  asm("{ .reg .u64 t; cvta.to.shared.u64 t, %1; cvt.u32.u64 %0, t; }"
      : "=r"(a) : "l"(p));
  return a;
}

__device__ __forceinline__ void split4A(float f, __half* dst, int stride) {
  __half a0 = __float2half_rn(f);
  float a0f = __half2float(a0);
  __half a1 = __float2half_rn((f - a0f) * 64.0f);
  float a1f = __half2float(a1);
  dst[0]          = a0;
  dst[stride]     = __float2half_rn(a0f * 0.03125f);
  dst[2 * stride] = a1;
  dst[3 * stride] = __float2half_rn(a1f * 2.44140625e-4f);
}

__device__ __forceinline__ void split4B(float f, __half* dst, int stride) {
  __half b0 = __float2half_rn(f);
  float b0f = __half2float(b0);
  __half b1 = __float2half_rn((f - b0f) * 64.0f);
  float b1f = __half2float(b1);
  dst[0]          = b0;
  dst[stride]     = __float2half_rn(b1f * 0.5f);
  dst[2 * stride] = __float2half_rn(b0f * 0.015625f);
  dst[3 * stride] = b1;
}

// Threefry2x32 (exact JAX constants)
__device__ __forceinline__ void tf2x32(uint32_t k0, uint32_t k1,
                                       uint32_t x0, uint32_t x1,
                                       uint32_t& o0, uint32_t& o1) {
  uint32_t ks2 = k0 ^ k1 ^ 0x1BD11BDAu;
#define TF_ROT(x,r) (((x) << (r)) | ((x) >> (32 - (r))))
#define TF_RND(r) { x0 += x1; x1 = TF_ROT(x1, r); x1 ^= x0; }
  x0 += k0; x1 += k1;
  TF_RND(13) TF_RND(15) TF_RND(26) TF_RND(6)   x0 += k1;  x1 += ks2 + 1u;
  TF_RND(17) TF_RND(29) TF_RND(16) TF_RND(24)  x0 += ks2; x1 += k0 + 2u;
  TF_RND(13) TF_RND(15) TF_RND(26) TF_RND(6)   x0 += k0;  x1 += k1 + 3u;
  TF_RND(17) TF_RND(29) TF_RND(16) TF_RND(24)  x0 += k1;  x1 += ks2 + 4u;
  TF_RND(13) TF_RND(15) TF_RND(26) TF_RND(6)   x0 += ks2; x1 += k0 + 5u;
  o0 = x0; o1 = x1;
#undef TF_RND
#undef TF_ROT
}

__device__ __forceinline__ float sigf(float x) { return 1.0f / (1.0f + expf(-x)); }

// perm_n -> original gates column: pn = hg*64 + gate*16 + hl
__device__ __forceinline__ int perm_orig(int pn) {
  int hg = pn >> 6, gate = (pn >> 4) & 3, hl = pn & 15;
  return gate * 512 + hg * 16 + hl;
}

// ---------------------------------------------------------------------------
// Setup kernels
// ---------------------------------------------------------------------------
template<int WHICH>   // 0: w_hh -> g_Whh (perm), 1: w_ih -> g_Wih (perm), 2: out_w -> g_Wo
__global__ __launch_bounds__(256) void k_split_w(const float* __restrict__ w) {
  __shared__ float t[32][33];
  const int bx = blockIdx.x, ky = blockIdx.y;     // bx<64, ky<16
  const int tx = threadIdx.x & 31, ty = threadIdx.x >> 5;
  const int col = (WHICH == 2) ? (bx * 32 + tx) : perm_orig(bx * 32 + tx);
#pragma unroll
  for (int r = 0; r < 4; r++) {
    int kl = ty + r * 8;
    t[kl][tx] = w[(size_t)(ky * 32 + kl) * 2048 + col];
  }
  __syncthreads();
  __half* G = (WHICH == 0) ? g_Whh : (WHICH == 1) ? g_Wih : g_Wo;
#pragma unroll
  for (int r = 0; r < 4; r++) {
    int nl = ty + r * 8;
    int pn = bx * 32 + nl;
    int k = ky * 32 + tx;
    split4B(t[tx][nl], &G[(size_t)pn * 2048 + k], 512);
  }
}

// emb rows 0..2047, sos row 2048, zeros 2049..2175 -> A-plane layout
__global__ __launch_bounds__(256) void k_split_emb(const float* __restrict__ emb,
                                                   const float* __restrict__ sos) {
  int idx = blockIdx.x * 256 + threadIdx.x;       // 2176*512
  int v = idx >> 9, c = idx & 511;
  float f = (v < 2048) ? emb[idx] : (v == 2048 ? sos[c] : 0.0f);
  split4A(f, &g_E6p[(size_t)v * 2048 + c], 512);
}

__global__ __launch_bounds__(256) void k_init(const float* __restrict__ b_ih,
                                              const float* __restrict__ b_hh,
                                              float* __restrict__ out) {
  int idx = blockIdx.x * 256 + threadIdx.x;       // 512*2048
  int b = idx >> 11, v = idx & 2047;
  out[(size_t)PROBS_OFF + ((size_t)b * LP1 + 32) * VV + v] = 1.0f;
  if (v < 512) g_c[b * 512 + v] = 0.0f;
  if (b == 0) {
    int o = perm_orig(v);
    g_bg[v] = b_ih[o] + b_hh[o];
  }
  if (v == 0) {
    g_sym[b] = 2048;   // sos row of g_EG for step 0
    out[SEQ_OFF  + b * LP1 + 32] = 0.0f;
    out[LOGP_OFF + b * LP1 + 32] = 0.0f;
    out[ENT_OFF  + b * LP1 + 32] = 0.0f;
  }
}

// ---------------------------------------------------------------------------
// SIMT fp32 GEMM for h0 (once): h0 = x @ agent_w + agent_b -> g_Ah[0] planes
// ---------------------------------------------------------------------------
__global__ __launch_bounds__(256) void k_h0(const float* __restrict__ A,
                                            const float* __restrict__ W,
                                            const float* __restrict__ bias) {
  const int N = 512, K = 1024;
  __shared__ float As[64][17];
  __shared__ float Ws[16][64];
  const int tid = threadIdx.x;
  const int tx = tid & 15, ty = tid >> 4;
  const int m0 = blockIdx.y * 64, n0 = blockIdx.x * 64;
  float acc[4][4];
#pragma unroll
  for (int r = 0; r < 4; r++)
#pragma unroll
    for (int c = 0; c < 4; c++) acc[r][c] = 0.f;
  for (int kb = 0; kb < K; kb += 16) {
#pragma unroll
    for (int i = 0; i < 4; i++) {
      int idx = tid + i * 256;
      As[idx >> 4][idx & 15] = A[(size_t)(m0 + (idx >> 4)) * K + kb + (idx & 15)];
    }
#pragma unroll
    for (int i = 0; i < 4; i++) {
      int idx = tid + i * 256;
      Ws[idx >> 6][idx & 63] = W[(size_t)(kb + (idx >> 6)) * N + n0 + (idx & 63)];
    }
    __syncthreads();
#pragma unroll
    for (int k = 0; k < 16; k++) {
      float a[4], w[4];
#pragma unroll
      for (int r = 0; r < 4; r++) a[r] = As[ty * 4 + r][k];
#pragma unroll
      for (int c = 0; c < 4; c++) w[c] = Ws[k][tx * 4 + c];
#pragma unroll
      for (int r = 0; r < 4; r++)
#pragma unroll
        for (int c = 0; c < 4; c++) acc[r][c] = fmaf(a[r], w[c], acc[r][c]);
    }
    __syncthreads();
  }
#pragma unroll
  for (int r = 0; r < 4; r++)
#pragma unroll
    for (int c = 0; c < 4; c++) {
      int row = m0 + ty * 4 + r, col = n0 + tx * 4 + c;
      float hn = acc[r][c] + bias[col];
      split4A(hn, &g_Ah[0][(size_t)row * 2048 + col], 512);
    }
}

// ---------------------------------------------------------------------------
// fp16 HMMA GEMM, 128x64 tile, warp tile 16x64, BK=32, 4-stage cp.async.
// MODE 0: gates = h @ Whh, fused LSTM epilogue -> g_c, g_Ah[1-ain]
// MODE 1: logits = h @ Wo + out_b -> g_z
// MODE 2: EG = E6p @ Wih -> g_EG (fp32)
// ---------------------------------------------------------------------------
#define LDM_X4(r0,r1,r2,r3,addr) \
  asm volatile("ldmatrix.sync.aligned.m8n8.x4.shared.b16 {%0,%1,%2,%3}, [%4];" \
               : "=r"(r0), "=r"(r1), "=r"(r2), "=r"(r3) : "r"(addr))
#define MMA16816(c0,c1,c2,c3,a0,a1,a2,a3,b0,b1) \
  asm volatile("mma.sync.aligned.m16n8k16.row.col.f32.f16.f16.f32 " \
               "{%0,%1,%2,%3}, {%4,%5,%6,%7}, {%8,%9}, {%0,%1,%2,%3};" \
               : "+f"(c0), "+f"(c1), "+f"(c2), "+f"(c3) \
               : "r"(a0), "r"(a1), "r"(a2), "r"(a3), "r"(b0), "r"(b1))

#define STG_STRIDE 15360           // A 128*40*2 + B 64*40*2
#define SMEM_G (4 * STG_STRIDE)

template<int MODE>
__global__ __launch_bounds__(256) void k_gemm(int ain, const float* __restrict__ ob) {
  constexpr int KT = 64;           // 2048 / 32
  const __half* __restrict__ A  = (MODE == 2) ? g_E6p : g_Ah[ain];
  const __half* __restrict__ Bt = (MODE == 0) ? g_Whh
                                 : (MODE == 1) ? g_Wo : g_Wih;

  extern __shared__ __half sm[];
  const uint32_t sbase = smem_to_u32(sm);

  const int tid = threadIdx.x;
  const int l = tid & 31, w = tid >> 5;
  const int m0 = blockIdx.y * 128, n0 = blockIdx.x * 64;

  float acc[8][4];
#pragma unroll
  for (int a = 0; a < 8; a++)
#pragma unroll
    for (int c = 0; c < 4; c++) acc[a][c] = 0.f;

  const int lr = tid >> 2, lc = (tid & 3) * 8;

#define LOAD_STAGE(st, kt) do {                                               \
    int kk_ = (kt) * 32;                                                      \
    uint32_t da_ = sbase + (st) * STG_STRIDE + (lr * 40 + lc) * 2;            \
    const __half* ga_ = A + (size_t)(m0 + lr) * 2048 + kk_ + lc;              \
    asm volatile("cp.async.cg.shared.global [%0], [%1], 16;"                  \
                 :: "r"(da_), "l"(ga_));                                      \
    asm volatile("cp.async.cg.shared.global [%0], [%1], 16;"                  \
                 :: "r"(da_ + 64 * 80), "l"(ga_ + (size_t)64 * 2048));        \
    uint32_t db_ = sbase + (st) * STG_STRIDE + 10240 + (lr * 40 + lc) * 2;    \
    const __half* gb_ = Bt + (size_t)(n0 + lr) * 2048 + kk_ + lc;             \
    asm volatile("cp.async.cg.shared.global [%0], [%1], 16;"                  \
                 :: "r"(db_), "l"(gb_));                                      \
    asm volatile("cp.async.commit_group;");                                   \
  } while (0)

  LOAD_STAGE(0, 0);
  LOAD_STAGE(1, 1);
  LOAD_STAGE(2, 2);

  for (int kt = 0; kt < KT; kt++) {
    if (kt < KT - 2)       asm volatile("cp.async.wait_group 2;");
    else if (kt == KT - 2) asm volatile("cp.async.wait_group 1;");
    else                   asm volatile("cp.async.wait_group 0;");
    __syncthreads();
    if (kt + 3 < KT) LOAD_STAGE((kt + 3) & 3, kt + 3);

    const uint32_t abase = sbase + (kt & 3) * STG_STRIDE;
    const uint32_t bbase = abase + 10240;
#pragma unroll
    for (int kk = 0; kk < 32; kk += 16) {
      uint32_t af[4];
      {
        int row = w * 16 + (l & 15);
        int col = kk + (l >> 4) * 8;
        LDM_X4(af[0], af[1], af[2], af[3], abase + (row * 40 + col) * 2);
      }
      uint32_t bf[4][4];
#pragma unroll
      for (int f2 = 0; f2 < 4; f2++) {
        int row = f2 * 16 + ((l >> 4) << 3) + (l & 7);
        int col = kk + ((l >> 3) & 1) * 8;
        LDM_X4(bf[f2][0], bf[f2][1], bf[f2][2], bf[f2][3],
               bbase + (row * 40 + col) * 2);
      }
#pragma unroll
      for (int fn = 0; fn < 8; fn++) {
        uint32_t b0 = bf[fn >> 1][(fn & 1) * 2];
        uint32_t b1 = bf[fn >> 1][(fn & 1) * 2 + 1];
        MMA16816(acc[fn][0], acc[fn][1], acc[fn][2], acc[fn][3],
                 af[0], af[1], af[2], af[3], b0, b1);
      }
    }
  }
#undef LOAD_STAGE

  const int r0 = m0 + w * 16 + (l >> 2);
  const int cb = (l & 3) * 2;

  if (MODE == 2) {
#pragma unroll
    for (int fn = 0; fn < 8; fn++) {
      int c = n0 + fn * 8 + cb;
      g_EG[(size_t)r0 * 2048 + c]           = acc[fn][0];
      g_EG[(size_t)r0 * 2048 + c + 1]       = acc[fn][1];
      g_EG[(size_t)(r0 + 8) * 2048 + c]     = acc[fn][2];
      g_EG[(size_t)(r0 + 8) * 2048 + c + 1] = acc[fn][3];
    }
  } else if (MODE == 1) {
#pragma unroll
    for (int fn = 0; fn < 8; fn++) {
      int c = n0 + fn * 8 + cb;
      g_z[(size_t)r0 * 2048 + c]           = acc[fn][0] + ob[c];
      g_z[(size_t)r0 * 2048 + c + 1]       = acc[fn][1] + ob[c + 1];
      g_z[(size_t)(r0 + 8) * 2048 + c]     = acc[fn][2] + ob[c];
      g_z[(size_t)(r0 + 8) * 2048 + c + 1] = acc[fn][3] + ob[c + 1];
    }
  } else {
    // Fused LSTM epilogue. Thread owns (row r0, r0+8) x (2 hl-groups) x 2.
    __half* Aout = g_Ah[1 - ain];
#pragma unroll
    for (int rr = 0; rr < 2; rr++) {
      int row = r0 + rr * 8;
      int sym = g_sym[row];
      const float* __restrict__ eg = &g_EG[(size_t)sym * 2048 + n0];
      const float* __restrict__ bg = &g_bg[n0];
#pragma unroll
      for (int p = 0; p < 2; p++) {
#pragma unroll
        for (int j = 0; j < 2; j++) {
          int hl = p * 8 + cb + j;
          float gi = acc[0 + p][rr * 2 + j] + eg[hl]      + bg[hl];
          float gf = acc[2 + p][rr * 2 + j] + eg[16 + hl] + bg[16 + hl];
          float gg = acc[4 + p][rr * 2 + j] + eg[32 + hl] + bg[32 + hl];
          float go = acc[6 + p][rr * 2 + j] + eg[48 + hl] + bg[48 + hl];
          int hglob = (n0 >> 2) + hl;
          int ci = row * 512 + hglob;
          float cold = g_c[ci];
          float cn = sigf(gf) * cold + sigf(gi) * tanhf(gg);
          float hn = sigf(go) * tanhf(cn);
          g_c[ci] = cn;
          split4A(hn, &Aout[(size_t)row * 2048 + hglob], 512);
        }
      }
    }
  }
}

// ---------------------------------------------------------------------------
// Sampler: log-softmax over g_z, probs/entropy, Gumbel-argmax (JAX
// partitionable threefry), record sym.
// ---------------------------------------------------------------------------
__global__ __launch_bounds__(256) void k_sample(float* __restrict__ out, int t) {
  const int b = blockIdx.x;
  const int tid = threadIdx.x;
  const float* __restrict__ z = &g_z[(size_t)b * VV];

  float zv[8];
#pragma unroll
  for (int j = 0; j < 8; j++) zv[j] = z[tid + j * 256];

  __shared__ float red[256];
  __shared__ float rv[256];
  __shared__ int   ri[256];

  float m = zv[0];
#pragma unroll
  for (int j = 1; j < 8; j++) m = fmaxf(m, zv[j]);
  red[tid] = m; __syncthreads();
  for (int s = 128; s > 0; s >>= 1) {
    if (tid < s) red[tid] = fmaxf(red[tid], red[tid + s]);
    __syncthreads();
  }
  const float M = red[0]; __syncthreads();

  float ssum = 0.f;
#pragma unroll
  for (int j = 0; j < 8; j++) ssum += __expf(zv[j] - M);
  red[tid] = ssum; __syncthreads();
  for (int s = 128; s > 0; s >>= 1) {
    if (tid < s) red[tid] += red[tid + s];
    __syncthreads();
  }
  const float lse = logf(red[0]); __syncthreads();

  // key chain: key0=(0,1); per step: new_key=tf(key,(0,0)), subkey=tf(key,(0,1))
  uint32_t k0 = 0u, k1 = 1u, sk0 = 0u, sk1 = 0u;
  for (int st = 0; st <= t; st++) {
    uint32_t n0, n1, s0, s1;
    tf2x32(k0, k1, 0u, 0u, n0, n1);
    tf2x32(k0, k1, 0u, 1u, s0, s1);
    sk0 = s0; sk1 = s1; k0 = n0; k1 = n1;
  }

  float entp = 0.f;
  float bestv = -INFINITY;
  int   besti = VV;
  const size_t probs_row = (size_t)PROBS_OFF + ((size_t)b * LP1 + t) * VV;
#pragma unroll
  for (int j = 0; j < 8; j++) {
    int v = tid + j * 256;
    float lsm = zv[j] - M - lse;
    float pr = __expf(lsm);
    out[probs_row + v] = pr;
    entp += pr * lsm;
    uint32_t o0, o1;
    tf2x32(sk0, sk1, 0u, (uint32_t)(b * VV + v), o0, o1);
    uint32_t bits = o0 ^ o1;
    float f = __uint_as_float((bits >> 9) | 0x3f800000u) - 1.0f;
    float u = fmaxf(f, 1.1754943508222875e-38f);
    float gum = -logf(-logf(u));
    float val = gum + lsm;
    if (val > bestv || (val == bestv && v < besti)) { bestv = val; besti = v; }
  }

  red[tid] = entp; __syncthreads();
  for (int s = 128; s > 0; s >>= 1) {
    if (tid < s) red[tid] += red[tid + s];
    __syncthreads();
  }
  const float ENT = red[0]; __syncthreads();

  rv[tid] = bestv; ri[tid] = besti; __syncthreads();
  for (int s = 128; s > 0; s >>= 1) {
    if (tid < s) {
      if (rv[tid + s] > rv[tid] ||
          (rv[tid + s] == rv[tid] && ri[tid + s] < ri[tid])) {
        rv[tid] = rv[tid + s]; ri[tid] = ri[tid + s];
      }
    }
    __syncthreads();
  }
  if (tid == 0) {
    int sym = ri[0];
    g_sym[b] = sym;
    out[SEQ_OFF  + b * LP1 + t] = (float)sym;
    out[LOGP_OFF + b * LP1 + t] = z[sym] - M - lse;
    out[ENT_OFF  + b * LP1 + t] = -ENT;
  }
}

// ---------------------------------------------------------------------------
extern "C" void kernel_launch(void* const* d_in, const int* in_sizes, int n_in,
                              void* d_out, int out_size) {
  const float* x       = (const float*)d_in[0];
  const float* agent_w = (const float*)d_in[1];
  const float* agent_b = (const float*)d_in[2];
  const float* sos     = (const float*)d_in[3];
  const float* emb     = (const float*)d_in[4];
  const float* w_ih    = (const float*)d_in[5];
  const float* w_hh    = (const float*)d_in[6];
  const float* b_ih    = (const float*)d_in[7];
  const float* b_hh    = (const float*)d_in[8];
  const float* out_w   = (const float*)d_in[9];
  const float* out_b   = (const float*)d_in[10];
  float* out = (float*)d_out;

  cudaFuncSetAttribute(k_gemm<0>, cudaFuncAttributeMaxDynamicSharedMemorySize, SMEM_G);
  cudaFuncSetAttribute(k_gemm<1>, cudaFuncAttributeMaxDynamicSharedMemorySize, SMEM_G);
  cudaFuncSetAttribute(k_gemm<2>, cudaFuncAttributeMaxDynamicSharedMemorySize, SMEM_G);

  k_init<<<4096, 256>>>(b_ih, b_hh, out);
  k_split_emb<<<4352, 256>>>(emb, sos);
  k_split_w<0><<<dim3(64, 16), 256>>>(w_hh);
  k_split_w<1><<<dim3(64, 16), 256>>>(w_ih);
  k_split_w<2><<<dim3(64, 16), 256>>>(out_w);
  k_gemm<2><<<dim3(32, 17), 256, SMEM_G>>>(0, nullptr);   // EG precompute
  k_h0<<<dim3(8, 8), 256>>>(x, agent_w, agent_b);

  for (int t = 0; t < 32; t++) {
    int ain = t & 1;         // h_{t-1} lives in g_Ah[ain]; h_t -> g_Ah[1-ain]
    k_gemm<0><<<dim3(32, 4), 256, SMEM_G>>>(ain, nullptr);   // gates + LSTM
    k_gemm<1><<<dim3(32, 4), 256, SMEM_G>>>(1 - ain, out_b); // logits
    k_sample<<<512, 256>>>(out, t);
  }
}

// round 10
// speedup vs baseline: 2.4337x; 1.1499x over previous
#include <cuda_runtime.h>
#include <cuda_fp16.h>
#include <cstdint>
#include <math.h>

#define VV 2048
#define LP1 33
#define SEQ_OFF   0
#define PROBS_OFF (512*33)
#define LOGP_OFF  (PROBS_OFF + 512*33*2048)
#define ENT_OFF   (LOGP_OFF + 512*33)

// fp16 x 4-product split, K' = 4*512 = 2048.
// A segs: [a0 | a0*2^-5 | a1s | a1s*2^-12],  a1s = fp16((h-a0)*2^6)
// B segs: [b0 | b1s*2^-1 | b0*2^-6 | b1s],   b1s = fp16((w-w0)*2^6)

// ---------------------------------------------------------------------------
// Persistent device scratch
// ---------------------------------------------------------------------------
__device__ __half g_Whh[2048 * 2048];   // w_hh B-planes, [perm_n][2048]
__device__ __half g_Wih[2048 * 2048];   // w_ih B-planes, [perm_n][2048]
__device__ __half g_Wo [2048 * 2048];   // out_w B-planes, [n][2048]
__device__ __half g_E6p[2176 * 2048];   // emb(+sos@2048, zero pad) A-planes
__device__ __half g_Ah [2][512 * 2048]; // h A-planes, ping-pong
__device__ float g_EG[2176 * 2048];     // (emb|sos) @ w_ih, perm n, fp32
__device__ float g_z [512 * 2048];      // logits
__device__ float g_gum[512 * 2048];     // per-step Gumbel field
__device__ float g_bg[2048];            // b_ih+b_hh in perm order
__device__ float g_c [512 * 512];
__device__ float g_h0f[512 * 512];
__device__ int   g_sym[512];

// ---------------------------------------------------------------------------
__device__ __forceinline__ uint32_t smem_to_u32(const void* p) {
  uint32_t a;
  asm("{ .reg .u64 t; cvta.to.shared.u64 t, %1; cvt.u32.u64 %0, t; }"
      : "=r"(a) : "l"(p));
  return a;
}

__device__ __forceinline__ void split4A(float f, __half* dst, int stride) {
  __half a0 = __float2half_rn(f);
  float a0f = __half2float(a0);
  __half a1 = __float2half_rn((f - a0f) * 64.0f);
  float a1f = __half2float(a1);
  dst[0]          = a0;
  dst[stride]     = __float2half_rn(a0f * 0.03125f);
  dst[2 * stride] = a1;
  dst[3 * stride] = __float2half_rn(a1f * 2.44140625e-4f);
}

__device__ __forceinline__ void split4B(float f, __half* dst, int stride) {
  __half b0 = __float2half_rn(f);
  float b0f = __half2float(b0);
  __half b1 = __float2half_rn((f - b0f) * 64.0f);
  float b1f = __half2float(b1);
  dst[0]          = b0;
  dst[stride]     = __float2half_rn(b1f * 0.5f);
  dst[2 * stride] = __float2half_rn(b0f * 0.015625f);
  dst[3 * stride] = b1;
}

// Threefry2x32 (exact JAX constants) — device
__device__ __forceinline__ void tf2x32(uint32_t k0, uint32_t k1,
                                       uint32_t x0, uint32_t x1,
                                       uint32_t& o0, uint32_t& o1) {
  uint32_t ks2 = k0 ^ k1 ^ 0x1BD11BDAu;
#define TF_ROT(x,r) (((x) << (r)) | ((x) >> (32 - (r))))
#define TF_RND(r) { x0 += x1; x1 = TF_ROT(x1, r); x1 ^= x0; }
  x0 += k0; x1 += k1;
  TF_RND(13) TF_RND(15) TF_RND(26) TF_RND(6)   x0 += k1;  x1 += ks2 + 1u;
  TF_RND(17) TF_RND(29) TF_RND(16) TF_RND(24)  x0 += ks2; x1 += k0 + 2u;
  TF_RND(13) TF_RND(15) TF_RND(26) TF_RND(6)   x0 += k0;  x1 += k1 + 3u;
  TF_RND(17) TF_RND(29) TF_RND(16) TF_RND(24)  x0 += k1;  x1 += ks2 + 4u;
  TF_RND(13) TF_RND(15) TF_RND(26) TF_RND(6)   x0 += ks2; x1 += k0 + 5u;
  o0 = x0; o1 = x1;
#undef TF_RND
#undef TF_ROT
}

// host version (per-step subkey chain)
static void h_tf2x32(uint32_t k0, uint32_t k1, uint32_t x0, uint32_t x1,
                     uint32_t& o0, uint32_t& o1) {
  uint32_t ks2 = k0 ^ k1 ^ 0x1BD11BDAu;
#define TF_ROT(x,r) (((x) << (r)) | ((x) >> (32 - (r))))
#define TF_RND(r) { x0 += x1; x1 = TF_ROT(x1, r); x1 ^= x0; }
  x0 += k0; x1 += k1;
  TF_RND(13) TF_RND(15) TF_RND(26) TF_RND(6)   x0 += k1;  x1 += ks2 + 1u;
  TF_RND(17) TF_RND(29) TF_RND(16) TF_RND(24)  x0 += ks2; x1 += k0 + 2u;
  TF_RND(13) TF_RND(15) TF_RND(26) TF_RND(6)   x0 += k0;  x1 += k1 + 3u;
  TF_RND(17) TF_RND(29) TF_RND(16) TF_RND(24)  x0 += k1;  x1 += ks2 + 4u;
  TF_RND(13) TF_RND(15) TF_RND(26) TF_RND(6)   x0 += ks2; x1 += k0 + 5u;
  o0 = x0; o1 = x1;
#undef TF_RND
#undef TF_ROT
}

__device__ __forceinline__ float sigf(float x) { return 1.0f / (1.0f + expf(-x)); }

// perm_n -> original gates column: pn = hg*64 + gate*16 + hl
__device__ __forceinline__ int perm_orig(int pn) {
  int hg = pn >> 6, gate = (pn >> 4) & 3, hl = pn & 15;
  return gate * 512 + hg * 16 + hl;
}

// ---------------------------------------------------------------------------
// Setup kernels
// ---------------------------------------------------------------------------
template<int WHICH>   // 0: w_hh, 1: w_ih (both perm), 2: out_w
__global__ __launch_bounds__(256) void k_split_w(const float* __restrict__ w) {
  __shared__ float t[32][33];
  const int bx = blockIdx.x, ky = blockIdx.y;     // bx<64, ky<16
  const int tx = threadIdx.x & 31, ty = threadIdx.x >> 5;
  const int col = (WHICH == 2) ? (bx * 32 + tx) : perm_orig(bx * 32 + tx);
#pragma unroll
  for (int r = 0; r < 4; r++) {
    int kl = ty + r * 8;
    t[kl][tx] = w[(size_t)(ky * 32 + kl) * 2048 + col];
  }
  __syncthreads();
  __half* G = (WHICH == 0) ? g_Whh : (WHICH == 1) ? g_Wih : g_Wo;
#pragma unroll
  for (int r = 0; r < 4; r++) {
    int nl = ty + r * 8;
    int pn = bx * 32 + nl;
    int k = ky * 32 + tx;
    split4B(t[tx][nl], &G[(size_t)pn * 2048 + k], 512);
  }
}

__global__ __launch_bounds__(256) void k_split_emb(const float* __restrict__ emb,
                                                   const float* __restrict__ sos) {
  int idx = blockIdx.x * 256 + threadIdx.x;       // 2176*512
  int v = idx >> 9, c = idx & 511;
  float f = (v < 2048) ? emb[idx] : (v == 2048 ? sos[c] : 0.0f);
  split4A(f, &g_E6p[(size_t)v * 2048 + c], 512);
}

__global__ __launch_bounds__(256) void k_init(const float* __restrict__ b_ih,
                                              const float* __restrict__ b_hh,
                                              float* __restrict__ out) {
  int idx = blockIdx.x * 256 + threadIdx.x;       // 512*2048
  int b = idx >> 11, v = idx & 2047;
  out[(size_t)PROBS_OFF + ((size_t)b * LP1 + 32) * VV + v] = 1.0f;
  if (v < 512) g_c[b * 512 + v] = 0.0f;
  if (b == 0) {
    int o = perm_orig(v);
    g_bg[v] = b_ih[o] + b_hh[o];
  }
  if (v == 0) {
    g_sym[b] = 2048;
    out[SEQ_OFF  + b * LP1 + 32] = 0.0f;
    out[LOGP_OFF + b * LP1 + 32] = 0.0f;
    out[ENT_OFF  + b * LP1 + 32] = 0.0f;
  }
}

// ---------------------------------------------------------------------------
// SIMT fp32 GEMM for h0 (once)
// ---------------------------------------------------------------------------
__global__ __launch_bounds__(256) void k_h0(const float* __restrict__ A,
                                            const float* __restrict__ W,
                                            const float* __restrict__ bias) {
  const int N = 512, K = 1024;
  __shared__ float As[64][17];
  __shared__ float Ws[16][64];
  const int tid = threadIdx.x;
  const int tx = tid & 15, ty = tid >> 4;
  const int m0 = blockIdx.y * 64, n0 = blockIdx.x * 64;
  float acc[4][4];
#pragma unroll
  for (int r = 0; r < 4; r++)
#pragma unroll
    for (int c = 0; c < 4; c++) acc[r][c] = 0.f;
  for (int kb = 0; kb < K; kb += 16) {
#pragma unroll
    for (int i = 0; i < 4; i++) {
      int idx = tid + i * 256;
      As[idx >> 4][idx & 15] = A[(size_t)(m0 + (idx >> 4)) * K + kb + (idx & 15)];
    }
#pragma unroll
    for (int i = 0; i < 4; i++) {
      int idx = tid + i * 256;
      Ws[idx >> 6][idx & 63] = W[(size_t)(kb + (idx >> 6)) * N + n0 + (idx & 63)];
    }
    __syncthreads();
#pragma unroll
    for (int k = 0; k < 16; k++) {
      float a[4], w[4];
#pragma unroll
      for (int r = 0; r < 4; r++) a[r] = As[ty * 4 + r][k];
#pragma unroll
      for (int c = 0; c < 4; c++) w[c] = Ws[k][tx * 4 + c];
#pragma unroll
      for (int r = 0; r < 4; r++)
#pragma unroll
        for (int c = 0; c < 4; c++) acc[r][c] = fmaf(a[r], w[c], acc[r][c]);
    }
    __syncthreads();
  }
#pragma unroll
  for (int r = 0; r < 4; r++)
#pragma unroll
    for (int c = 0; c < 4; c++) {
      int row = m0 + ty * 4 + r, col = n0 + tx * 4 + c;
      float hn = acc[r][c] + bias[col];
      split4A(hn, &g_Ah[0][(size_t)row * 2048 + col], 512);
    }
}

// ---------------------------------------------------------------------------
// fp16 HMMA GEMM, 128x64 tile, BK=32, 4-stage cp.async.
// MODE 0/1: grid (32,8) — by<4: GEMM CTAs; by>=4: 128 Gumbel-hash CTAs that
// fill the tensor-idle issue slots computing this step's threefry field
// (MODE 0 -> rows 0..255, MODE 1 -> rows 256..511 of g_gum).
// MODE 0: gates = h @ Whh + fused LSTM -> g_c, g_Ah[1-ain]
// MODE 1: logits = h @ Wo + out_b -> g_z
// MODE 2: EG = E6p @ Wih -> g_EG (grid (32,17), no gumbel)
// ---------------------------------------------------------------------------
#define LDM_X4(r0,r1,r2,r3,addr) \
  asm volatile("ldmatrix.sync.aligned.m8n8.x4.shared.b16 {%0,%1,%2,%3}, [%4];" \
               : "=r"(r0), "=r"(r1), "=r"(r2), "=r"(r3) : "r"(addr))
#define MMA16816(c0,c1,c2,c3,a0,a1,a2,a3,b0,b1) \
  asm volatile("mma.sync.aligned.m16n8k16.row.col.f32.f16.f16.f32 " \
               "{%0,%1,%2,%3}, {%4,%5,%6,%7}, {%8,%9}, {%0,%1,%2,%3};" \
               : "+f"(c0), "+f"(c1), "+f"(c2), "+f"(c3) \
               : "r"(a0), "r"(a1), "r"(a2), "r"(a3), "r"(b0), "r"(b1))

#define STG_STRIDE 15360           // A 128*40*2 + B 64*40*2
#define SMEM_G (4 * STG_STRIDE)

template<int MODE>
__global__ __launch_bounds__(256) void k_gemm(int ain, const float* __restrict__ ob,
                                              uint32_t sk0, uint32_t sk1) {
  if (MODE < 2 && blockIdx.y >= 4) {
    // Gumbel CTAs: 128 CTAs x 256 thr = 32768 lanes, 16 elems each (half field)
    int gid = ((blockIdx.y - 4) * 32 + blockIdx.x) * 256 + threadIdx.x;
    const uint32_t base = (MODE == 1) ? 524288u : 0u;
#pragma unroll
    for (int e = 0; e < 16; e++) {
      uint32_t idx = base + (uint32_t)e * 32768u + (uint32_t)gid;
      uint32_t o0, o1;
      tf2x32(sk0, sk1, 0u, idx, o0, o1);
      uint32_t bits = o0 ^ o1;
      float f = __uint_as_float((bits >> 9) | 0x3f800000u) - 1.0f;
      float u = fmaxf(f, 1.1754943508222875e-38f);
      g_gum[idx] = -__logf(-__logf(u));
    }
    return;
  }

  constexpr int KT = 64;           // 2048 / 32
  const __half* __restrict__ A  = (MODE == 2) ? g_E6p : g_Ah[ain];
  const __half* __restrict__ Bt = (MODE == 0) ? g_Whh
                                 : (MODE == 1) ? g_Wo : g_Wih;

  extern __shared__ __half sm[];
  const uint32_t sbase = smem_to_u32(sm);

  const int tid = threadIdx.x;
  const int l = tid & 31, w = tid >> 5;
  const int m0 = blockIdx.y * 128, n0 = blockIdx.x * 64;

  float acc[8][4];
#pragma unroll
  for (int a = 0; a < 8; a++)
#pragma unroll
    for (int c = 0; c < 4; c++) acc[a][c] = 0.f;

  const int lr = tid >> 2, lc = (tid & 3) * 8;

#define LOAD_STAGE(st, kt) do {                                               \
    int kk_ = (kt) * 32;                                                      \
    uint32_t da_ = sbase + (st) * STG_STRIDE + (lr * 40 + lc) * 2;            \
    const __half* ga_ = A + (size_t)(m0 + lr) * 2048 + kk_ + lc;              \
    asm volatile("cp.async.cg.shared.global [%0], [%1], 16;"                  \
                 :: "r"(da_), "l"(ga_));                                      \
    asm volatile("cp.async.cg.shared.global [%0], [%1], 16;"                  \
                 :: "r"(da_ + 64 * 80), "l"(ga_ + (size_t)64 * 2048));        \
    uint32_t db_ = sbase + (st) * STG_STRIDE + 10240 + (lr * 40 + lc) * 2;    \
    const __half* gb_ = Bt + (size_t)(n0 + lr) * 2048 + kk_ + lc;             \
    asm volatile("cp.async.cg.shared.global [%0], [%1], 16;"                  \
                 :: "r"(db_), "l"(gb_));                                      \
    asm volatile("cp.async.commit_group;");                                   \
  } while (0)

  LOAD_STAGE(0, 0);
  LOAD_STAGE(1, 1);
  LOAD_STAGE(2, 2);

  for (int kt = 0; kt < KT; kt++) {
    if (kt < KT - 2)       asm volatile("cp.async.wait_group 2;");
    else if (kt == KT - 2) asm volatile("cp.async.wait_group 1;");
    else                   asm volatile("cp.async.wait_group 0;");
    __syncthreads();
    if (kt + 3 < KT) LOAD_STAGE((kt + 3) & 3, kt + 3);

    const uint32_t abase = sbase + (kt & 3) * STG_STRIDE;
    const uint32_t bbase = abase + 10240;
#pragma unroll
    for (int kk = 0; kk < 32; kk += 16) {
      uint32_t af[4];
      {
        int row = w * 16 + (l & 15);
        int col = kk + (l >> 4) * 8;
        LDM_X4(af[0], af[1], af[2], af[3], abase + (row * 40 + col) * 2);
      }
      uint32_t bf[4][4];
#pragma unroll
      for (int f2 = 0; f2 < 4; f2++) {
        int row = f2 * 16 + ((l >> 4) << 3) + (l & 7);
        int col = kk + ((l >> 3) & 1) * 8;
        LDM_X4(bf[f2][0], bf[f2][1], bf[f2][2], bf[f2][3],
               bbase + (row * 40 + col) * 2);
      }
#pragma unroll
      for (int fn = 0; fn < 8; fn++) {
        uint32_t b0 = bf[fn >> 1][(fn & 1) * 2];
        uint32_t b1 = bf[fn >> 1][(fn & 1) * 2 + 1];
        MMA16816(acc[fn][0], acc[fn][1], acc[fn][2], acc[fn][3],
                 af[0], af[1], af[2], af[3], b0, b1);
      }
    }
  }
#undef LOAD_STAGE

  const int r0 = m0 + w * 16 + (l >> 2);
  const int cb = (l & 3) * 2;

  if (MODE == 2) {
#pragma unroll
    for (int fn = 0; fn < 8; fn++) {
      int c = n0 + fn * 8 + cb;
      g_EG[(size_t)r0 * 2048 + c]           = acc[fn][0];
      g_EG[(size_t)r0 * 2048 + c + 1]       = acc[fn][1];
      g_EG[(size_t)(r0 + 8) * 2048 + c]     = acc[fn][2];
      g_EG[(size_t)(r0 + 8) * 2048 + c + 1] = acc[fn][3];
    }
  } else if (MODE == 1) {
#pragma unroll
    for (int fn = 0; fn < 8; fn++) {
      int c = n0 + fn * 8 + cb;
      g_z[(size_t)r0 * 2048 + c]           = acc[fn][0] + ob[c];
      g_z[(size_t)r0 * 2048 + c + 1]       = acc[fn][1] + ob[c + 1];
      g_z[(size_t)(r0 + 8) * 2048 + c]     = acc[fn][2] + ob[c];
      g_z[(size_t)(r0 + 8) * 2048 + c + 1] = acc[fn][3] + ob[c + 1];
    }
  } else {
    __half* Aout = g_Ah[1 - ain];
#pragma unroll
    for (int rr = 0; rr < 2; rr++) {
      int row = r0 + rr * 8;
      int sym = g_sym[row];
      const float* __restrict__ eg = &g_EG[(size_t)sym * 2048 + n0];
      const float* __restrict__ bg = &g_bg[n0];
#pragma unroll
      for (int p = 0; p < 2; p++) {
#pragma unroll
        for (int j = 0; j < 2; j++) {
          int hl = p * 8 + cb + j;
          float gi = acc[0 + p][rr * 2 + j] + eg[hl]      + bg[hl];
          float gf = acc[2 + p][rr * 2 + j] + eg[16 + hl] + bg[16 + hl];
          float gg = acc[4 + p][rr * 2 + j] + eg[32 + hl] + bg[32 + hl];
          float go = acc[6 + p][rr * 2 + j] + eg[48 + hl] + bg[48 + hl];
          int hglob = (n0 >> 2) + hl;
          int ci = row * 512 + hglob;
          float cold = g_c[ci];
          float cn = sigf(gf) * cold + sigf(gi) * tanhf(gg);
          float hn = sigf(go) * tanhf(cn);
          g_c[ci] = cn;
          split4A(hn, &Aout[(size_t)row * 2048 + hglob], 512);
        }
      }
    }
  }
}

// ---------------------------------------------------------------------------
// Sampler: log-softmax over g_z, probs/entropy, Gumbel-argmax from g_gum.
// ---------------------------------------------------------------------------
__global__ __launch_bounds__(256) void k_sample(float* __restrict__ out, int t) {
  const int b = blockIdx.x;
  const int tid = threadIdx.x;
  const float* __restrict__ z   = &g_z[(size_t)b * VV];
  const float* __restrict__ gum = &g_gum[(size_t)b * VV];

  float zv[8];
#pragma unroll
  for (int j = 0; j < 8; j++) zv[j] = z[tid + j * 256];

  __shared__ float red[256];
  __shared__ float rv[256];
  __shared__ int   ri[256];

  float m = zv[0];
#pragma unroll
  for (int j = 1; j < 8; j++) m = fmaxf(m, zv[j]);
  red[tid] = m; __syncthreads();
  for (int s = 128; s > 0; s >>= 1) {
    if (tid < s) red[tid] = fmaxf(red[tid], red[tid + s]);
    __syncthreads();
  }
  const float M = red[0]; __syncthreads();

  float ssum = 0.f;
#pragma unroll
  for (int j = 0; j < 8; j++) ssum += __expf(zv[j] - M);
  red[tid] = ssum; __syncthreads();
  for (int s = 128; s > 0; s >>= 1) {
    if (tid < s) red[tid] += red[tid + s];
    __syncthreads();
  }
  const float lse = logf(red[0]); __syncthreads();

  float entp = 0.f;
  float bestv = -INFINITY;
  int   besti = VV;
  const size_t probs_row = (size_t)PROBS_OFF + ((size_t)b * LP1 + t) * VV;
#pragma unroll
  for (int j = 0; j < 8; j++) {
    int v = tid + j * 256;
    float lsm = zv[j] - M - lse;
    float pr = __expf(lsm);
    out[probs_row + v] = pr;
    entp += pr * lsm;
    float val = gum[v] + lsm;
    if (val > bestv || (val == bestv && v < besti)) { bestv = val; besti = v; }
  }

  red[tid] = entp; __syncthreads();
  for (int s = 128; s > 0; s >>= 1) {
    if (tid < s) red[tid] += red[tid + s];
    __syncthreads();
  }
  const float ENT = red[0]; __syncthreads();

  rv[tid] = bestv; ri[tid] = besti; __syncthreads();
  for (int s = 128; s > 0; s >>= 1) {
    if (tid < s) {
      if (rv[tid + s] > rv[tid] ||
          (rv[tid + s] == rv[tid] && ri[tid + s] < ri[tid])) {
        rv[tid] = rv[tid + s]; ri[tid] = ri[tid + s];
      }
    }
    __syncthreads();
  }
  if (tid == 0) {
    int sym = ri[0];
    g_sym[b] = sym;
    out[SEQ_OFF  + b * LP1 + t] = (float)sym;
    out[LOGP_OFF + b * LP1 + t] = z[sym] - M - lse;
    out[ENT_OFF  + b * LP1 + t] = -ENT;
  }
}

// ---------------------------------------------------------------------------
extern "C" void kernel_launch(void* const* d_in, const int* in_sizes, int n_in,
                              void* d_out, int out_size) {
  const float* x       = (const float*)d_in[0];
  const float* agent_w = (const float*)d_in[1];
  const float* agent_b = (const float*)d_in[2];
  const float* sos     = (const float*)d_in[3];
  const float* emb     = (const float*)d_in[4];
  const float* w_ih    = (const float*)d_in[5];
  const float* w_hh    = (const float*)d_in[6];
  const float* b_ih    = (const float*)d_in[7];
  const float* b_hh    = (const float*)d_in[8];
  const float* out_w   = (const float*)d_in[9];
  const float* out_b   = (const float*)d_in[10];
  float* out = (float*)d_out;

  cudaFuncSetAttribute(k_gemm<0>, cudaFuncAttributeMaxDynamicSharedMemorySize, SMEM_G);
  cudaFuncSetAttribute(k_gemm<1>, cudaFuncAttributeMaxDynamicSharedMemorySize, SMEM_G);
  cudaFuncSetAttribute(k_gemm<2>, cudaFuncAttributeMaxDynamicSharedMemorySize, SMEM_G);

  // per-step threefry subkeys: key0=(0,1); new_key=tf(key,(0,0)), subkey=tf(key,(0,1))
  uint32_t sk0[32], sk1[32];
  {
    uint32_t k0 = 0u, k1 = 1u;
    for (int t = 0; t < 32; t++) {
      uint32_t n0, n1, s0, s1;
      h_tf2x32(k0, k1, 0u, 0u, n0, n1);
      h_tf2x32(k0, k1, 0u, 1u, s0, s1);
      sk0[t] = s0; sk1[t] = s1; k0 = n0; k1 = n1;
    }
  }

  k_init<<<4096, 256>>>(b_ih, b_hh, out);
  k_split_emb<<<4352, 256>>>(emb, sos);
  k_split_w<0><<<dim3(64, 16), 256>>>(w_hh);
  k_split_w<1><<<dim3(64, 16), 256>>>(w_ih);
  k_split_w<2><<<dim3(64, 16), 256>>>(out_w);
  k_gemm<2><<<dim3(32, 17), 256, SMEM_G>>>(0, nullptr, 0u, 0u);  // EG precompute
  k_h0<<<dim3(8, 8), 256>>>(x, agent_w, agent_b);

  for (int t = 0; t < 32; t++) {
    int ain = t & 1;
    k_gemm<0><<<dim3(32, 8), 256, SMEM_G>>>(ain, nullptr, sk0[t], sk1[t]);   // gates+LSTM ∥ gumbel lo
    k_gemm<1><<<dim3(32, 8), 256, SMEM_G>>>(1 - ain, out_b, sk0[t], sk1[t]); // logits ∥ gumbel hi
    k_sample<<<512, 256>>>(out, t);
  }
}

// round 11
// speedup vs baseline: 2.9743x; 1.2221x over previous
#include <cuda_runtime.h>
#include <cuda_fp16.h>
#include <cstdint>
#include <math.h>

#define VV 2048
#define LP1 33
#define SEQ_OFF   0
#define PROBS_OFF (512*33)
#define LOGP_OFF  (PROBS_OFF + 512*33*2048)
#define ENT_OFF   (LOGP_OFF + 512*33)

// fp16 x 4-product split, K' = 4*512 = 2048.
// A segs: [a0 | a0*2^-5 | a1s | a1s*2^-12],  a1s = fp16((h-a0)*2^6)
// B segs: [b0 | b1s*2^-1 | b0*2^-6 | b1s],   b1s = fp16((w-w0)*2^6)

// ---------------------------------------------------------------------------
// Persistent device scratch
// ---------------------------------------------------------------------------
__device__ __half g_Whh[2048 * 2048];   // w_hh B-planes, [perm_n][2048]
__device__ __half g_Wih[2048 * 2048];   // w_ih B-planes, [perm_n][2048]
__device__ __half g_Wo [2048 * 2048];   // out_w B-planes, [n][2048]
__device__ __half g_E6p[2176 * 2048];   // emb(+sos@2048, zero pad) A-planes
__device__ __half g_Ah [2][512 * 2048]; // h A-planes, ping-pong
__device__ float g_EG[2176 * 2048];     // (emb|sos) @ w_ih, perm n, fp32
__device__ float g_z [512 * 2048];      // logits of current step
__device__ float g_P [512 * 2048];      // pre-gates (h @ Whh), perm n
__device__ float g_gum[2][512 * 2048];  // Gumbel field, ping-pong
__device__ float g_bg[2048];            // b_ih+b_hh in perm order
__device__ float g_c [512 * 512];

// ---------------------------------------------------------------------------
__device__ __forceinline__ uint32_t smem_to_u32(const void* p) {
  uint32_t a;
  asm("{ .reg .u64 t; cvta.to.shared.u64 t, %1; cvt.u32.u64 %0, t; }"
      : "=r"(a) : "l"(p));
  return a;
}

__device__ __forceinline__ void split4A(float f, __half* dst, int stride) {
  __half a0 = __float2half_rn(f);
  float a0f = __half2float(a0);
  __half a1 = __float2half_rn((f - a0f) * 64.0f);
  float a1f = __half2float(a1);
  dst[0]          = a0;
  dst[stride]     = __float2half_rn(a0f * 0.03125f);
  dst[2 * stride] = a1;
  dst[3 * stride] = __float2half_rn(a1f * 2.44140625e-4f);
}

__device__ __forceinline__ void split4B(float f, __half* dst, int stride) {
  __half b0 = __float2half_rn(f);
  float b0f = __half2float(b0);
  __half b1 = __float2half_rn((f - b0f) * 64.0f);
  float b1f = __half2float(b1);
  dst[0]          = b0;
  dst[stride]     = __float2half_rn(b1f * 0.5f);
  dst[2 * stride] = __float2half_rn(b0f * 0.015625f);
  dst[3 * stride] = b1;
}

// Threefry2x32 (exact JAX constants) — device
__device__ __forceinline__ void tf2x32(uint32_t k0, uint32_t k1,
                                       uint32_t x0, uint32_t x1,
                                       uint32_t& o0, uint32_t& o1) {
  uint32_t ks2 = k0 ^ k1 ^ 0x1BD11BDAu;
#define TF_ROT(x,r) (((x) << (r)) | ((x) >> (32 - (r))))
#define TF_RND(r) { x0 += x1; x1 = TF_ROT(x1, r); x1 ^= x0; }
  x0 += k0; x1 += k1;
  TF_RND(13) TF_RND(15) TF_RND(26) TF_RND(6)   x0 += k1;  x1 += ks2 + 1u;
  TF_RND(17) TF_RND(29) TF_RND(16) TF_RND(24)  x0 += ks2; x1 += k0 + 2u;
  TF_RND(13) TF_RND(15) TF_RND(26) TF_RND(6)   x0 += k0;  x1 += k1 + 3u;
  TF_RND(17) TF_RND(29) TF_RND(16) TF_RND(24)  x0 += k1;  x1 += ks2 + 4u;
  TF_RND(13) TF_RND(15) TF_RND(26) TF_RND(6)   x0 += ks2; x1 += k0 + 5u;
  o0 = x0; o1 = x1;
#undef TF_RND
#undef TF_ROT
}

static void h_tf2x32(uint32_t k0, uint32_t k1, uint32_t x0, uint32_t x1,
                     uint32_t& o0, uint32_t& o1) {
  uint32_t ks2 = k0 ^ k1 ^ 0x1BD11BDAu;
#define TF_ROT(x,r) (((x) << (r)) | ((x) >> (32 - (r))))
#define TF_RND(r) { x0 += x1; x1 = TF_ROT(x1, r); x1 ^= x0; }
  x0 += k0; x1 += k1;
  TF_RND(13) TF_RND(15) TF_RND(26) TF_RND(6)   x0 += k1;  x1 += ks2 + 1u;
  TF_RND(17) TF_RND(29) TF_RND(16) TF_RND(24)  x0 += ks2; x1 += k0 + 2u;
  TF_RND(13) TF_RND(15) TF_RND(26) TF_RND(6)   x0 += k0;  x1 += k1 + 3u;
  TF_RND(17) TF_RND(29) TF_RND(16) TF_RND(24)  x0 += k1;  x1 += ks2 + 4u;
  TF_RND(13) TF_RND(15) TF_RND(26) TF_RND(6)   x0 += ks2; x1 += k0 + 5u;
  o0 = x0; o1 = x1;
#undef TF_RND
#undef TF_ROT
}

__device__ __forceinline__ float sigf(float x) { return 1.0f / (1.0f + expf(-x)); }

// perm_n -> original gates column: pn = hg*64 + gate*16 + hl
__device__ __forceinline__ int perm_orig(int pn) {
  int hg = pn >> 6, gate = (pn >> 4) & 3, hl = pn & 15;
  return gate * 512 + hg * 16 + hl;
}

// Gumbel value from threefry bits (JAX-compatible)
__device__ __forceinline__ float gumbel_of(uint32_t sk0, uint32_t sk1, uint32_t idx) {
  uint32_t o0, o1;
  tf2x32(sk0, sk1, 0u, idx, o0, o1);
  uint32_t bits = o0 ^ o1;
  float f = __uint_as_float((bits >> 9) | 0x3f800000u) - 1.0f;
  float u = fmaxf(f, 1.1754943508222875e-38f);
  return -__logf(-__logf(u));
}

// LSTM pointwise for one (b, h): reads P/EG/bg rows, updates c, returns h_new
__device__ __forceinline__ float lstm_one(const float* __restrict__ P,
                                          const float* __restrict__ eg,
                                          int b, int hh) {
  int hg = hh >> 4, hl = hh & 15;
  int pn = hg * 64 + hl;
  float gi = P[pn]      + eg[pn]      + g_bg[pn];
  float gf = P[pn + 16] + eg[pn + 16] + g_bg[pn + 16];
  float gg = P[pn + 32] + eg[pn + 32] + g_bg[pn + 32];
  float go = P[pn + 48] + eg[pn + 48] + g_bg[pn + 48];
  int ci = b * 512 + hh;
  float cold = g_c[ci];
  float cn = sigf(gf) * cold + sigf(gi) * tanhf(gg);
  float hn = sigf(go) * tanhf(cn);
  g_c[ci] = cn;
  return hn;
}

// ---------------------------------------------------------------------------
// Setup kernels
// ---------------------------------------------------------------------------
// merged weight splitter: z = 0 w_hh(perm), 1 w_ih(perm), 2 out_w
__global__ __launch_bounds__(256) void k_split_wall(const float* __restrict__ whh,
                                                    const float* __restrict__ wih,
                                                    const float* __restrict__ ow) {
  __shared__ float t[32][33];
  const int bx = blockIdx.x, ky = blockIdx.y, which = blockIdx.z;
  const int tx = threadIdx.x & 31, ty = threadIdx.x >> 5;
  const float* w = (which == 0) ? whh : (which == 1) ? wih : ow;
  const int col = (which == 2) ? (bx * 32 + tx) : perm_orig(bx * 32 + tx);
#pragma unroll
  for (int r = 0; r < 4; r++) {
    int kl = ty + r * 8;
    t[kl][tx] = w[(size_t)(ky * 32 + kl) * 2048 + col];
  }
  __syncthreads();
  __half* G = (which == 0) ? g_Whh : (which == 1) ? g_Wih : g_Wo;
#pragma unroll
  for (int r = 0; r < 4; r++) {
    int nl = ty + r * 8;
    int pn = bx * 32 + nl;
    int k = ky * 32 + tx;
    split4B(t[tx][nl], &G[(size_t)pn * 2048 + k], 512);
  }
}

__global__ __launch_bounds__(256) void k_split_emb(const float* __restrict__ emb,
                                                   const float* __restrict__ sos) {
  int idx = blockIdx.x * 256 + threadIdx.x;       // 2176*512
  int v = idx >> 9, c = idx & 511;
  float f = (v < 2048) ? emb[idx] : (v == 2048 ? sos[c] : 0.0f);
  split4A(f, &g_E6p[(size_t)v * 2048 + c], 512);
}

__global__ __launch_bounds__(256) void k_init(const float* __restrict__ b_ih,
                                              const float* __restrict__ b_hh,
                                              float* __restrict__ out) {
  int idx = blockIdx.x * 256 + threadIdx.x;       // 512*2048
  int b = idx >> 11, v = idx & 2047;
  out[(size_t)PROBS_OFF + ((size_t)b * LP1 + 32) * VV + v] = 1.0f;
  if (v < 512) g_c[b * 512 + v] = 0.0f;
  if (b == 0) {
    int o = perm_orig(v);
    g_bg[v] = b_ih[o] + b_hh[o];
  }
  if (v == 0) {
    out[SEQ_OFF  + b * LP1 + 32] = 0.0f;
    out[LOGP_OFF + b * LP1 + 32] = 0.0f;
    out[ENT_OFF  + b * LP1 + 32] = 0.0f;
  }
}

// ---------------------------------------------------------------------------
// SIMT fp32 GEMM for h0 (once): h0 -> g_Ah[1]
// ---------------------------------------------------------------------------
__global__ __launch_bounds__(256) void k_h0(const float* __restrict__ A,
                                            const float* __restrict__ W,
                                            const float* __restrict__ bias) {
  const int N = 512, K = 1024;
  __shared__ float As[64][17];
  __shared__ float Ws[16][64];
  const int tid = threadIdx.x;
  const int tx = tid & 15, ty = tid >> 4;
  const int m0 = blockIdx.y * 64, n0 = blockIdx.x * 64;
  float acc[4][4];
#pragma unroll
  for (int r = 0; r < 4; r++)
#pragma unroll
    for (int c = 0; c < 4; c++) acc[r][c] = 0.f;
  for (int kb = 0; kb < K; kb += 16) {
#pragma unroll
    for (int i = 0; i < 4; i++) {
      int idx = tid + i * 256;
      As[idx >> 4][idx & 15] = A[(size_t)(m0 + (idx >> 4)) * K + kb + (idx & 15)];
    }
#pragma unroll
    for (int i = 0; i < 4; i++) {
      int idx = tid + i * 256;
      Ws[idx >> 6][idx & 63] = W[(size_t)(kb + (idx >> 6)) * N + n0 + (idx & 63)];
    }
    __syncthreads();
#pragma unroll
    for (int k = 0; k < 16; k++) {
      float a[4], w[4];
#pragma unroll
      for (int r = 0; r < 4; r++) a[r] = As[ty * 4 + r][k];
#pragma unroll
      for (int c = 0; c < 4; c++) w[c] = Ws[k][tx * 4 + c];
#pragma unroll
      for (int r = 0; r < 4; r++)
#pragma unroll
        for (int c = 0; c < 4; c++) acc[r][c] = fmaf(a[r], w[c], acc[r][c]);
    }
    __syncthreads();
  }
#pragma unroll
  for (int r = 0; r < 4; r++)
#pragma unroll
    for (int c = 0; c < 4; c++) {
      int row = m0 + ty * 4 + r, col = n0 + tx * 4 + c;
      float hn = acc[r][c] + bias[col];
      split4A(hn, &g_Ah[1][(size_t)row * 2048 + col], 512);
    }
}

// ---------------------------------------------------------------------------
// fp16 HMMA GEMM core (128x64 tile, BK=32, 4-stage cp.async)
// ---------------------------------------------------------------------------
#define LDM_X4(r0,r1,r2,r3,addr) \
  asm volatile("ldmatrix.sync.aligned.m8n8.x4.shared.b16 {%0,%1,%2,%3}, [%4];" \
               : "=r"(r0), "=r"(r1), "=r"(r2), "=r"(r3) : "r"(addr))
#define MMA16816(c0,c1,c2,c3,a0,a1,a2,a3,b0,b1) \
  asm volatile("mma.sync.aligned.m16n8k16.row.col.f32.f16.f16.f32 " \
               "{%0,%1,%2,%3}, {%4,%5,%6,%7}, {%8,%9}, {%0,%1,%2,%3};" \
               : "+f"(c0), "+f"(c1), "+f"(c2), "+f"(c3) \
               : "r"(a0), "r"(a1), "r"(a2), "r"(a3), "r"(b0), "r"(b1))

#define STG_STRIDE 15360           // A 128*40*2 + B 64*40*2
#define SMEM_G (4 * STG_STRIDE)

__device__ __forceinline__ void gemm_core(const __half* __restrict__ A,
                                          const __half* __restrict__ Bt,
                                          int m0, int n0, float acc[8][4]) {
  constexpr int KT = 64;
  extern __shared__ __half sm[];
  const uint32_t sbase = smem_to_u32(sm);
  const int tid = threadIdx.x;
  const int l = tid & 31, w = tid >> 5;
  const int lr = tid >> 2, lc = (tid & 3) * 8;

#define LOAD_STAGE(st, kt) do {                                               \
    int kk_ = (kt) * 32;                                                      \
    uint32_t da_ = sbase + (st) * STG_STRIDE + (lr * 40 + lc) * 2;            \
    const __half* ga_ = A + (size_t)(m0 + lr) * 2048 + kk_ + lc;              \
    asm volatile("cp.async.cg.shared.global [%0], [%1], 16;"                  \
                 :: "r"(da_), "l"(ga_));                                      \
    asm volatile("cp.async.cg.shared.global [%0], [%1], 16;"                  \
                 :: "r"(da_ + 64 * 80), "l"(ga_ + (size_t)64 * 2048));        \
    uint32_t db_ = sbase + (st) * STG_STRIDE + 10240 + (lr * 40 + lc) * 2;    \
    const __half* gb_ = Bt + (size_t)(n0 + lr) * 2048 + kk_ + lc;             \
    asm volatile("cp.async.cg.shared.global [%0], [%1], 16;"                  \
                 :: "r"(db_), "l"(gb_));                                      \
    asm volatile("cp.async.commit_group;");                                   \
  } while (0)

  LOAD_STAGE(0, 0);
  LOAD_STAGE(1, 1);
  LOAD_STAGE(2, 2);

  for (int kt = 0; kt < KT; kt++) {
    if (kt < KT - 2)       asm volatile("cp.async.wait_group 2;");
    else if (kt == KT - 2) asm volatile("cp.async.wait_group 1;");
    else                   asm volatile("cp.async.wait_group 0;");
    __syncthreads();
    if (kt + 3 < KT) LOAD_STAGE((kt + 3) & 3, kt + 3);

    const uint32_t abase = sbase + (kt & 3) * STG_STRIDE;
    const uint32_t bbase = abase + 10240;
#pragma unroll
    for (int kk = 0; kk < 32; kk += 16) {
      uint32_t af[4];
      {
        int row = w * 16 + (l & 15);
        int col = kk + (l >> 4) * 8;
        LDM_X4(af[0], af[1], af[2], af[3], abase + (row * 40 + col) * 2);
      }
      uint32_t bf[4][4];
#pragma unroll
      for (int f2 = 0; f2 < 4; f2++) {
        int row = f2 * 16 + ((l >> 4) << 3) + (l & 7);
        int col = kk + ((l >> 3) & 1) * 8;
        LDM_X4(bf[f2][0], bf[f2][1], bf[f2][2], bf[f2][3],
               bbase + (row * 40 + col) * 2);
      }
#pragma unroll
      for (int fn = 0; fn < 8; fn++) {
        uint32_t b0 = bf[fn >> 1][(fn & 1) * 2];
        uint32_t b1 = bf[fn >> 1][(fn & 1) * 2 + 1];
        MMA16816(acc[fn][0], acc[fn][1], acc[fn][2], acc[fn][3],
                 af[0], af[1], af[2], af[3], b0, b1);
      }
    }
  }
#undef LOAD_STAGE
}

// Merged step GEMM: grid (32, 8). by<4 -> z = h@Wo + ob; by>=4 -> P = h@Whh.
__global__ __launch_bounds__(256) void k_mgemm(int ain, const float* __restrict__ ob) {
  const int half = blockIdx.y >> 2;
  const int m0 = (blockIdx.y & 3) * 128, n0 = blockIdx.x * 64;
  float acc[8][4];
#pragma unroll
  for (int a = 0; a < 8; a++)
#pragma unroll
    for (int c = 0; c < 4; c++) acc[a][c] = 0.f;

  gemm_core(g_Ah[ain], half ? g_Whh : g_Wo, m0, n0, acc);

  const int l = threadIdx.x & 31, w = threadIdx.x >> 5;
  const int r0 = m0 + w * 16 + (l >> 2);
  const int cb = (l & 3) * 2;
  if (half) {
#pragma unroll
    for (int fn = 0; fn < 8; fn++) {
      int c = n0 + fn * 8 + cb;
      g_P[(size_t)r0 * 2048 + c]           = acc[fn][0];
      g_P[(size_t)r0 * 2048 + c + 1]       = acc[fn][1];
      g_P[(size_t)(r0 + 8) * 2048 + c]     = acc[fn][2];
      g_P[(size_t)(r0 + 8) * 2048 + c + 1] = acc[fn][3];
    }
  } else {
#pragma unroll
    for (int fn = 0; fn < 8; fn++) {
      int c = n0 + fn * 8 + cb;
      g_z[(size_t)r0 * 2048 + c]           = acc[fn][0] + ob[c];
      g_z[(size_t)r0 * 2048 + c + 1]       = acc[fn][1] + ob[c + 1];
      g_z[(size_t)(r0 + 8) * 2048 + c]     = acc[fn][2] + ob[c];
      g_z[(size_t)(r0 + 8) * 2048 + c + 1] = acc[fn][3] + ob[c + 1];
    }
  }
}

// EG precompute: g_EG = E6p @ Wih, grid (32, 17)
__global__ __launch_bounds__(256) void k_eg() {
  const int m0 = blockIdx.y * 128, n0 = blockIdx.x * 64;
  float acc[8][4];
#pragma unroll
  for (int a = 0; a < 8; a++)
#pragma unroll
    for (int c = 0; c < 4; c++) acc[a][c] = 0.f;
  gemm_core(g_E6p, g_Wih, m0, n0, acc);
  const int l = threadIdx.x & 31, w = threadIdx.x >> 5;
  const int r0 = m0 + w * 16 + (l >> 2);
  const int cb = (l & 3) * 2;
#pragma unroll
  for (int fn = 0; fn < 8; fn++) {
    int c = n0 + fn * 8 + cb;
    g_EG[(size_t)r0 * 2048 + c]           = acc[fn][0];
    g_EG[(size_t)r0 * 2048 + c + 1]       = acc[fn][1];
    g_EG[(size_t)(r0 + 8) * 2048 + c]     = acc[fn][2];
    g_EG[(size_t)(r0 + 8) * 2048 + c + 1] = acc[fn][3];
  }
}

// ---------------------------------------------------------------------------
// LSTM0: iteration-0 LSTM (sym = sos row 2048) -> g_Ah[0]; hash gum[0].
// ---------------------------------------------------------------------------
__global__ __launch_bounds__(256) void k_lstm0(uint32_t sk0, uint32_t sk1) {
  const int b = blockIdx.x, tid = threadIdx.x;
  const float* __restrict__ P = &g_P[(size_t)b * 2048];
  const float* __restrict__ eg = &g_EG[(size_t)2048 * 2048];
#pragma unroll
  for (int r = 0; r < 2; r++) {
    int hh = tid + r * 256;
    float hn = lstm_one(P, eg, b, hh);
    split4A(hn, &g_Ah[0][(size_t)b * 2048 + hh], 512);
  }
#pragma unroll
  for (int j = 0; j < 8; j++) {
    uint32_t idx = (uint32_t)(b * 2048 + tid + j * 256);
    g_gum[0][idx] = gumbel_of(sk0, sk1, idx);
  }
}

// ---------------------------------------------------------------------------
// Sampler(i): softmax/probs/entropy/argmax on z (gum[i&1]); then LSTM(i+1)
// (P + EG[sym]) -> g_Ah[(i+1)&1]; then hash gum[(i+1)&1] with next subkey.
// ---------------------------------------------------------------------------
__global__ __launch_bounds__(256) void k_sample(float* __restrict__ out, int t,
                                                uint32_t nsk0, uint32_t nsk1) {
  const int b = blockIdx.x;
  const int tid = threadIdx.x;
  const float* __restrict__ z   = &g_z[(size_t)b * VV];
  const float* __restrict__ gum = &g_gum[t & 1][(size_t)b * VV];

  float zv[8];
#pragma unroll
  for (int j = 0; j < 8; j++) zv[j] = z[tid + j * 256];

  __shared__ float red[256];
  __shared__ float rv[256];
  __shared__ int   ri[256];
  __shared__ int   s_sym;

  float m = zv[0];
#pragma unroll
  for (int j = 1; j < 8; j++) m = fmaxf(m, zv[j]);
  red[tid] = m; __syncthreads();
  for (int s = 128; s > 0; s >>= 1) {
    if (tid < s) red[tid] = fmaxf(red[tid], red[tid + s]);
    __syncthreads();
  }
  const float M = red[0]; __syncthreads();

  float ssum = 0.f;
#pragma unroll
  for (int j = 0; j < 8; j++) ssum += __expf(zv[j] - M);
  red[tid] = ssum; __syncthreads();
  for (int s = 128; s > 0; s >>= 1) {
    if (tid < s) red[tid] += red[tid + s];
    __syncthreads();
  }
  const float lse = logf(red[0]); __syncthreads();

  float entp = 0.f;
  float bestv = -INFINITY;
  int   besti = VV;
  const size_t probs_row = (size_t)PROBS_OFF + ((size_t)b * LP1 + t) * VV;
#pragma unroll
  for (int j = 0; j < 8; j++) {
    int v = tid + j * 256;
    float lsm = zv[j] - M - lse;
    float pr = __expf(lsm);
    out[probs_row + v] = pr;
    entp += pr * lsm;
    float val = gum[v] + lsm;
    if (val > bestv || (val == bestv && v < besti)) { bestv = val; besti = v; }
  }

  red[tid] = entp; __syncthreads();
  for (int s = 128; s > 0; s >>= 1) {
    if (tid < s) red[tid] += red[tid + s];
    __syncthreads();
  }
  const float ENT = red[0]; __syncthreads();

  rv[tid] = bestv; ri[tid] = besti; __syncthreads();
  for (int s = 128; s > 0; s >>= 1) {
    if (tid < s) {
      if (rv[tid + s] > rv[tid] ||
          (rv[tid + s] == rv[tid] && ri[tid + s] < ri[tid])) {
        rv[tid] = rv[tid + s]; ri[tid] = ri[tid + s];
      }
    }
    __syncthreads();
  }
  if (tid == 0) {
    int sym = ri[0];
    s_sym = sym;
    out[SEQ_OFF  + b * LP1 + t] = (float)sym;
    out[LOGP_OFF + b * LP1 + t] = z[sym] - M - lse;
    out[ENT_OFF  + b * LP1 + t] = -ENT;
  }
  __syncthreads();
  const int sym = s_sym;

  // LSTM(t+1): gates = P + EG[sym] + bg -> h planes for next step
  {
    const float* __restrict__ P = &g_P[(size_t)b * 2048];
    const float* __restrict__ eg = &g_EG[(size_t)sym * 2048];
    __half* Aout = &g_Ah[(t + 1) & 1][(size_t)b * 2048];
#pragma unroll
    for (int r = 0; r < 2; r++) {
      int hh = tid + r * 256;
      float hn = lstm_one(P, eg, b, hh);
      split4A(hn, &Aout[hh], 512);
    }
  }

  // hash next step's Gumbel field
  float* __restrict__ gd = &g_gum[(t + 1) & 1][0];
#pragma unroll
  for (int j = 0; j < 8; j++) {
    uint32_t idx = (uint32_t)(b * 2048 + tid + j * 256);
    gd[idx] = gumbel_of(nsk0, nsk1, idx);
  }
}

// ---------------------------------------------------------------------------
extern "C" void kernel_launch(void* const* d_in, const int* in_sizes, int n_in,
                              void* d_out, int out_size) {
  const float* x       = (const float*)d_in[0];
  const float* agent_w = (const float*)d_in[1];
  const float* agent_b = (const float*)d_in[2];
  const float* sos     = (const float*)d_in[3];
  const float* emb     = (const float*)d_in[4];
  const float* w_ih    = (const float*)d_in[5];
  const float* w_hh    = (const float*)d_in[6];
  const float* b_ih    = (const float*)d_in[7];
  const float* b_hh    = (const float*)d_in[8];
  const float* out_w   = (const float*)d_in[9];
  const float* out_b   = (const float*)d_in[10];
  float* out = (float*)d_out;

  cudaFuncSetAttribute(k_mgemm, cudaFuncAttributeMaxDynamicSharedMemorySize, SMEM_G);
  cudaFuncSetAttribute(k_eg,    cudaFuncAttributeMaxDynamicSharedMemorySize, SMEM_G);

  // per-step threefry subkeys (33: steps 0..31 + one spare for the tail hash)
  uint32_t sk0[33], sk1[33];
  {
    uint32_t k0 = 0u, k1 = 1u;
    for (int t = 0; t < 33; t++) {
      uint32_t n0, n1, s0, s1;
      h_tf2x32(k0, k1, 0u, 0u, n0, n1);
      h_tf2x32(k0, k1, 0u, 1u, s0, s1);
      sk0[t] = s0; sk1[t] = s1; k0 = n0; k1 = n1;
    }
  }

  k_init<<<4096, 256>>>(b_ih, b_hh, out);                 // 1
  k_split_emb<<<4352, 256>>>(emb, sos);                   // 2
  k_split_wall<<<dim3(64, 16, 3), 256>>>(w_hh, w_ih, out_w); // 3
  k_eg<<<dim3(32, 17), 256, SMEM_G>>>();                  // 4
  k_h0<<<dim3(8, 8), 256>>>(x, agent_w, agent_b);         // 5 -> g_Ah[1]
  k_mgemm<<<dim3(32, 8), 256, SMEM_G>>>(1, out_b);        // 6 (profiled): P_0
  k_lstm0<<<512, 256>>>(sk0[0], sk1[0]);                  // 7 -> H_1, gum_0

  for (int t = 0; t < 32; t++) {
    k_mgemm<<<dim3(32, 8), 256, SMEM_G>>>(t & 1, out_b);  // z_t, P_{t+1}
    k_sample<<<512, 256>>>(out, t, sk0[t + 1], sk1[t + 1]); // sym_t, LSTM, gum
  }
}

// round 12
// speedup vs baseline: 3.0892x; 1.0386x over previous
#include <cuda_runtime.h>
#include <cuda_fp16.h>
#include <cstdint>
#include <math.h>

#define VV 2048
#define LP1 33
#define SEQ_OFF   0
#define PROBS_OFF (512*33)
#define LOGP_OFF  (PROBS_OFF + 512*33*2048)
#define ENT_OFF   (LOGP_OFF + 512*33)

// fp16 x 4-product split, K' = 4*512 = 2048.
// A segs: [a0 | a0*2^-5 | a1s | a1s*2^-12],  a1s = fp16((h-a0)*2^6)
// B segs: [b0 | b1s*2^-1 | b0*2^-6 | b1s],   b1s = fp16((w-w0)*2^6)

// ---------------------------------------------------------------------------
// Persistent device scratch
// ---------------------------------------------------------------------------
__device__ __half g_Whh[2048 * 2048];   // w_hh B-planes, [perm_n][2048]
__device__ __half g_Wih[2048 * 2048];   // w_ih B-planes, [perm_n][2048]
__device__ __half g_Wo [2048 * 2048];   // out_w B-planes, [n][2048]
__device__ __half g_E6p[2176 * 2048];   // emb(+sos@2048, zero pad) A-planes
__device__ __half g_Ah [2][512 * 2048]; // h A-planes, ping-pong
__device__ float g_EG[2176 * 2048];     // (emb|sos) @ w_ih, perm n, fp32
__device__ float g_z [512 * 2048];      // logits of current step
__device__ float g_P [512 * 2048];      // pre-gates (h @ Whh), perm n
__device__ float g_gum[2][512 * 2048];  // Gumbel field, ping-pong
__device__ float g_bg[2048];            // b_ih+b_hh in perm order
__device__ float g_c [512 * 512];

// ---------------------------------------------------------------------------
__device__ __forceinline__ uint32_t smem_to_u32(const void* p) {
  uint32_t a;
  asm("{ .reg .u64 t; cvta.to.shared.u64 t, %1; cvt.u32.u64 %0, t; }"
      : "=r"(a) : "l"(p));
  return a;
}

__device__ __forceinline__ void split4A(float f, __half* dst, int stride) {
  __half a0 = __float2half_rn(f);
  float a0f = __half2float(a0);
  __half a1 = __float2half_rn((f - a0f) * 64.0f);
  float a1f = __half2float(a1);
  dst[0]          = a0;
  dst[stride]     = __float2half_rn(a0f * 0.03125f);
  dst[2 * stride] = a1;
  dst[3 * stride] = __float2half_rn(a1f * 2.44140625e-4f);
}

__device__ __forceinline__ void split4B(float f, __half* dst, int stride) {
  __half b0 = __float2half_rn(f);
  float b0f = __half2float(b0);
  __half b1 = __float2half_rn((f - b0f) * 64.0f);
  float b1f = __half2float(b1);
  dst[0]          = b0;
  dst[stride]     = __float2half_rn(b1f * 0.5f);
  dst[2 * stride] = __float2half_rn(b0f * 0.015625f);
  dst[3 * stride] = b1;
}

// Threefry2x32 (exact JAX constants) — device
__device__ __forceinline__ void tf2x32(uint32_t k0, uint32_t k1,
                                       uint32_t x0, uint32_t x1,
                                       uint32_t& o0, uint32_t& o1) {
  uint32_t ks2 = k0 ^ k1 ^ 0x1BD11BDAu;
#define TF_ROT(x,r) (((x) << (r)) | ((x) >> (32 - (r))))
#define TF_RND(r) { x0 += x1; x1 = TF_ROT(x1, r); x1 ^= x0; }
  x0 += k0; x1 += k1;
  TF_RND(13) TF_RND(15) TF_RND(26) TF_RND(6)   x0 += k1;  x1 += ks2 + 1u;
  TF_RND(17) TF_RND(29) TF_RND(16) TF_RND(24)  x0 += ks2; x1 += k0 + 2u;
  TF_RND(13) TF_RND(15) TF_RND(26) TF_RND(6)   x0 += k0;  x1 += k1 + 3u;
  TF_RND(17) TF_RND(29) TF_RND(16) TF_RND(24)  x0 += k1;  x1 += ks2 + 4u;
  TF_RND(13) TF_RND(15) TF_RND(26) TF_RND(6)   x0 += ks2; x1 += k0 + 5u;
  o0 = x0; o1 = x1;
#undef TF_RND
#undef TF_ROT
}

static void h_tf2x32(uint32_t k0, uint32_t k1, uint32_t x0, uint32_t x1,
                     uint32_t& o0, uint32_t& o1) {
  uint32_t ks2 = k0 ^ k1 ^ 0x1BD11BDAu;
#define TF_ROT(x,r) (((x) << (r)) | ((x) >> (32 - (r))))
#define TF_RND(r) { x0 += x1; x1 = TF_ROT(x1, r); x1 ^= x0; }
  x0 += k0; x1 += k1;
  TF_RND(13) TF_RND(15) TF_RND(26) TF_RND(6)   x0 += k1;  x1 += ks2 + 1u;
  TF_RND(17) TF_RND(29) TF_RND(16) TF_RND(24)  x0 += ks2; x1 += k0 + 2u;
  TF_RND(13) TF_RND(15) TF_RND(26) TF_RND(6)   x0 += k0;  x1 += k1 + 3u;
  TF_RND(17) TF_RND(29) TF_RND(16) TF_RND(24)  x0 += k1;  x1 += ks2 + 4u;
  TF_RND(13) TF_RND(15) TF_RND(26) TF_RND(6)   x0 += ks2; x1 += k0 + 5u;
  o0 = x0; o1 = x1;
#undef TF_RND
#undef TF_ROT
}

__device__ __forceinline__ float sigf(float x) { return 1.0f / (1.0f + expf(-x)); }

// perm_n -> original gates column: pn = hg*64 + gate*16 + hl
__device__ __forceinline__ int perm_orig(int pn) {
  int hg = pn >> 6, gate = (pn >> 4) & 3, hl = pn & 15;
  return gate * 512 + hg * 16 + hl;
}

// Gumbel value from threefry bits (JAX-compatible)
__device__ __forceinline__ float gumbel_of(uint32_t sk0, uint32_t sk1, uint32_t idx) {
  uint32_t o0, o1;
  tf2x32(sk0, sk1, 0u, idx, o0, o1);
  uint32_t bits = o0 ^ o1;
  float f = __uint_as_float((bits >> 9) | 0x3f800000u) - 1.0f;
  float u = fmaxf(f, 1.1754943508222875e-38f);
  return -__logf(-__logf(u));
}

// LSTM pointwise for one (b, h): reads P/EG/bg rows, updates c, returns h_new
__device__ __forceinline__ float lstm_one(const float* __restrict__ P,
                                          const float* __restrict__ eg,
                                          int b, int hh) {
  int hg = hh >> 4, hl = hh & 15;
  int pn = hg * 64 + hl;
  float gi = P[pn]      + eg[pn]      + g_bg[pn];
  float gf = P[pn + 16] + eg[pn + 16] + g_bg[pn + 16];
  float gg = P[pn + 32] + eg[pn + 32] + g_bg[pn + 32];
  float go = P[pn + 48] + eg[pn + 48] + g_bg[pn + 48];
  int ci = b * 512 + hh;
  float cold = g_c[ci];
  float cn = sigf(gf) * cold + sigf(gi) * tanhf(gg);
  float hn = sigf(go) * tanhf(cn);
  g_c[ci] = cn;
  return hn;
}

// ---------------------------------------------------------------------------
// Setup kernels
// ---------------------------------------------------------------------------
__global__ __launch_bounds__(256) void k_split_wall(const float* __restrict__ whh,
                                                    const float* __restrict__ wih,
                                                    const float* __restrict__ ow) {
  __shared__ float t[32][33];
  const int bx = blockIdx.x, ky = blockIdx.y, which = blockIdx.z;
  const int tx = threadIdx.x & 31, ty = threadIdx.x >> 5;
  const float* w = (which == 0) ? whh : (which == 1) ? wih : ow;
  const int col = (which == 2) ? (bx * 32 + tx) : perm_orig(bx * 32 + tx);
#pragma unroll
  for (int r = 0; r < 4; r++) {
    int kl = ty + r * 8;
    t[kl][tx] = w[(size_t)(ky * 32 + kl) * 2048 + col];
  }
  __syncthreads();
  __half* G = (which == 0) ? g_Whh : (which == 1) ? g_Wih : g_Wo;
#pragma unroll
  for (int r = 0; r < 4; r++) {
    int nl = ty + r * 8;
    int pn = bx * 32 + nl;
    int k = ky * 32 + tx;
    split4B(t[tx][nl], &G[(size_t)pn * 2048 + k], 512);
  }
}

__global__ __launch_bounds__(256) void k_split_emb(const float* __restrict__ emb,
                                                   const float* __restrict__ sos) {
  int idx = blockIdx.x * 256 + threadIdx.x;       // 2176*512
  int v = idx >> 9, c = idx & 511;
  float f = (v < 2048) ? emb[idx] : (v == 2048 ? sos[c] : 0.0f);
  split4A(f, &g_E6p[(size_t)v * 2048 + c], 512);
}

__global__ __launch_bounds__(256) void k_init(const float* __restrict__ b_ih,
                                              const float* __restrict__ b_hh,
                                              float* __restrict__ out) {
  int idx = blockIdx.x * 256 + threadIdx.x;       // 512*2048
  int b = idx >> 11, v = idx & 2047;
  out[(size_t)PROBS_OFF + ((size_t)b * LP1 + 32) * VV + v] = 1.0f;
  if (v < 512) g_c[b * 512 + v] = 0.0f;
  if (b == 0) {
    int o = perm_orig(v);
    g_bg[v] = b_ih[o] + b_hh[o];
  }
  if (v == 0) {
    out[SEQ_OFF  + b * LP1 + 32] = 0.0f;
    out[LOGP_OFF + b * LP1 + 32] = 0.0f;
    out[ENT_OFF  + b * LP1 + 32] = 0.0f;
  }
}

// ---------------------------------------------------------------------------
// SIMT fp32 GEMM for h0 (once): h0 -> g_Ah[1]
// ---------------------------------------------------------------------------
__global__ __launch_bounds__(256) void k_h0(const float* __restrict__ A,
                                            const float* __restrict__ W,
                                            const float* __restrict__ bias) {
  const int N = 512, K = 1024;
  __shared__ float As[64][17];
  __shared__ float Ws[16][64];
  const int tid = threadIdx.x;
  const int tx = tid & 15, ty = tid >> 4;
  const int m0 = blockIdx.y * 64, n0 = blockIdx.x * 64;
  float acc[4][4];
#pragma unroll
  for (int r = 0; r < 4; r++)
#pragma unroll
    for (int c = 0; c < 4; c++) acc[r][c] = 0.f;
  for (int kb = 0; kb < K; kb += 16) {
#pragma unroll
    for (int i = 0; i < 4; i++) {
      int idx = tid + i * 256;
      As[idx >> 4][idx & 15] = A[(size_t)(m0 + (idx >> 4)) * K + kb + (idx & 15)];
    }
#pragma unroll
    for (int i = 0; i < 4; i++) {
      int idx = tid + i * 256;
      Ws[idx >> 6][idx & 63] = W[(size_t)(kb + (idx >> 6)) * N + n0 + (idx & 63)];
    }
    __syncthreads();
#pragma unroll
    for (int k = 0; k < 16; k++) {
      float a[4], w[4];
#pragma unroll
      for (int r = 0; r < 4; r++) a[r] = As[ty * 4 + r][k];
#pragma unroll
      for (int c = 0; c < 4; c++) w[c] = Ws[k][tx * 4 + c];
#pragma unroll
      for (int r = 0; r < 4; r++)
#pragma unroll
        for (int c = 0; c < 4; c++) acc[r][c] = fmaf(a[r], w[c], acc[r][c]);
    }
    __syncthreads();
  }
#pragma unroll
  for (int r = 0; r < 4; r++)
#pragma unroll
    for (int c = 0; c < 4; c++) {
      int row = m0 + ty * 4 + r, col = n0 + tx * 4 + c;
      float hn = acc[r][c] + bias[col];
      split4A(hn, &g_Ah[1][(size_t)row * 2048 + col], 512);
    }
}

// ---------------------------------------------------------------------------
// fp16 HMMA GEMM core: 128x128 CTA tile, warp tile 64x32 (2x4 warps),
// BK=32, 4-stage cp.async. 6 ldmatrix.x4 per 16 MMAs per warp-kk.
// ---------------------------------------------------------------------------
#define LDM_X4(r0,r1,r2,r3,addr) \
  asm volatile("ldmatrix.sync.aligned.m8n8.x4.shared.b16 {%0,%1,%2,%3}, [%4];" \
               : "=r"(r0), "=r"(r1), "=r"(r2), "=r"(r3) : "r"(addr))
#define MMA16816(c0,c1,c2,c3,a0,a1,a2,a3,b0,b1) \
  asm volatile("mma.sync.aligned.m16n8k16.row.col.f32.f16.f16.f32 " \
               "{%0,%1,%2,%3}, {%4,%5,%6,%7}, {%8,%9}, {%0,%1,%2,%3};" \
               : "+f"(c0), "+f"(c1), "+f"(c2), "+f"(c3) \
               : "r"(a0), "r"(a1), "r"(a2), "r"(a3), "r"(b0), "r"(b1))

#define STG_STRIDE 20480           // A 128*40*2 + B 128*40*2
#define SMEM_G (4 * STG_STRIDE)

__device__ __forceinline__ void gemm_core(const __half* __restrict__ A,
                                          const __half* __restrict__ Bt,
                                          int m0, int n0, float acc[4][4][4]) {
  constexpr int KT = 64;
  extern __shared__ __half sm[];
  const uint32_t sbase = smem_to_u32(sm);
  const int tid = threadIdx.x;
  const int l = tid & 31, w = tid >> 5;
  const int wm = (w & 1) * 64, wn = (w >> 1) * 32;
  const int lr = tid >> 2, lc = (tid & 3) * 8;

#define LOAD_STAGE(st, kt) do {                                               \
    int kk_ = (kt) * 32;                                                      \
    uint32_t da_ = sbase + (st) * STG_STRIDE + (lr * 40 + lc) * 2;            \
    const __half* ga_ = A + (size_t)(m0 + lr) * 2048 + kk_ + lc;              \
    asm volatile("cp.async.cg.shared.global [%0], [%1], 16;"                  \
                 :: "r"(da_), "l"(ga_));                                      \
    asm volatile("cp.async.cg.shared.global [%0], [%1], 16;"                  \
                 :: "r"(da_ + 64 * 80), "l"(ga_ + (size_t)64 * 2048));        \
    uint32_t db_ = da_ + 10240;                                               \
    const __half* gb_ = Bt + (size_t)(n0 + lr) * 2048 + kk_ + lc;             \
    asm volatile("cp.async.cg.shared.global [%0], [%1], 16;"                  \
                 :: "r"(db_), "l"(gb_));                                      \
    asm volatile("cp.async.cg.shared.global [%0], [%1], 16;"                  \
                 :: "r"(db_ + 64 * 80), "l"(gb_ + (size_t)64 * 2048));        \
    asm volatile("cp.async.commit_group;");                                   \
  } while (0)

  LOAD_STAGE(0, 0);
  LOAD_STAGE(1, 1);
  LOAD_STAGE(2, 2);

  for (int kt = 0; kt < KT; kt++) {
    if (kt < KT - 2)       asm volatile("cp.async.wait_group 2;");
    else if (kt == KT - 2) asm volatile("cp.async.wait_group 1;");
    else                   asm volatile("cp.async.wait_group 0;");
    __syncthreads();
    if (kt + 3 < KT) LOAD_STAGE((kt + 3) & 3, kt + 3);

    const uint32_t abase = sbase + (kt & 3) * STG_STRIDE;
    const uint32_t bbase = abase + 10240;
#pragma unroll
    for (int kk = 0; kk < 32; kk += 16) {
      uint32_t af[4][4];
#pragma unroll
      for (int fm = 0; fm < 4; fm++) {
        int row = wm + fm * 16 + (l & 15);
        int col = kk + (l >> 4) * 8;
        LDM_X4(af[fm][0], af[fm][1], af[fm][2], af[fm][3],
               abase + (row * 40 + col) * 2);
      }
      uint32_t bf[2][4];
#pragma unroll
      for (int f2 = 0; f2 < 2; f2++) {
        int row = wn + f2 * 16 + ((l >> 4) << 3) + (l & 7);
        int col = kk + ((l >> 3) & 1) * 8;
        LDM_X4(bf[f2][0], bf[f2][1], bf[f2][2], bf[f2][3],
               bbase + (row * 40 + col) * 2);
      }
#pragma unroll
      for (int fm = 0; fm < 4; fm++)
#pragma unroll
        for (int fn = 0; fn < 4; fn++) {
          uint32_t b0 = bf[fn >> 1][(fn & 1) * 2];
          uint32_t b1 = bf[fn >> 1][(fn & 1) * 2 + 1];
          MMA16816(acc[fm][fn][0], acc[fm][fn][1], acc[fm][fn][2], acc[fm][fn][3],
                   af[fm][0], af[fm][1], af[fm][2], af[fm][3], b0, b1);
        }
    }
  }
#undef LOAD_STAGE
}

// store a 128x128 fp32 tile (optionally + bias)
__device__ __forceinline__ void store_tile(float* __restrict__ out, int m0, int n0,
                                           float acc[4][4][4],
                                           const float* __restrict__ bias) {
  const int l = threadIdx.x & 31, w = threadIdx.x >> 5;
  const int wm = (w & 1) * 64, wn = (w >> 1) * 32;
#pragma unroll
  for (int fm = 0; fm < 4; fm++)
#pragma unroll
    for (int fn = 0; fn < 4; fn++) {
      int r = m0 + wm + fm * 16 + (l >> 2);
      int c = n0 + wn + fn * 8 + (l & 3) * 2;
      float b0 = bias ? bias[c] : 0.f;
      float b1 = bias ? bias[c + 1] : 0.f;
      *(float2*)&out[(size_t)r * 2048 + c] =
          make_float2(acc[fm][fn][0] + b0, acc[fm][fn][1] + b1);
      *(float2*)&out[(size_t)(r + 8) * 2048 + c] =
          make_float2(acc[fm][fn][2] + b0, acc[fm][fn][3] + b1);
    }
}

// Merged step GEMM: grid (32, 4). bx<16 -> z = h@Wo + ob; bx>=16 -> P = h@Whh.
__global__ __launch_bounds__(256) void k_mgemm(int ain, const float* __restrict__ ob) {
  const int half = blockIdx.x >> 4;
  const int m0 = blockIdx.y * 128, n0 = (blockIdx.x & 15) * 128;
  float acc[4][4][4];
#pragma unroll
  for (int a = 0; a < 4; a++)
#pragma unroll
    for (int b = 0; b < 4; b++)
#pragma unroll
      for (int c = 0; c < 4; c++) acc[a][b][c] = 0.f;
  gemm_core(g_Ah[ain], half ? g_Whh : g_Wo, m0, n0, acc);
  if (half) store_tile(g_P, m0, n0, acc, nullptr);
  else      store_tile(g_z, m0, n0, acc, ob);
}

// EG precompute: g_EG = E6p @ Wih, grid (16, 17)
__global__ __launch_bounds__(256) void k_eg() {
  const int m0 = blockIdx.y * 128, n0 = blockIdx.x * 128;
  float acc[4][4][4];
#pragma unroll
  for (int a = 0; a < 4; a++)
#pragma unroll
    for (int b = 0; b < 4; b++)
#pragma unroll
      for (int c = 0; c < 4; c++) acc[a][b][c] = 0.f;
  gemm_core(g_E6p, g_Wih, m0, n0, acc);
  store_tile(g_EG, m0, n0, acc, nullptr);
}

// ---------------------------------------------------------------------------
// LSTM0: iteration-0 LSTM (sym = sos row 2048) -> g_Ah[0]; hash gum[0].
// ---------------------------------------------------------------------------
__global__ __launch_bounds__(256) void k_lstm0(uint32_t sk0, uint32_t sk1) {
  const int b = blockIdx.x, tid = threadIdx.x;
  const float* __restrict__ P = &g_P[(size_t)b * 2048];
  const float* __restrict__ eg = &g_EG[(size_t)2048 * 2048];
#pragma unroll
  for (int r = 0; r < 2; r++) {
    int hh = tid + r * 256;
    float hn = lstm_one(P, eg, b, hh);
    split4A(hn, &g_Ah[0][(size_t)b * 2048 + hh], 512);
  }
#pragma unroll
  for (int j = 0; j < 8; j++) {
    uint32_t idx = (uint32_t)(b * 2048 + tid + j * 256);
    g_gum[0][idx] = gumbel_of(sk0, sk1, idx);
  }
}

// ---------------------------------------------------------------------------
// Sampler(t): softmax/probs/entropy/argmax on z (gum[t&1]); then LSTM(t+1)
// -> g_Ah[(t+1)&1]; then hash gum[(t+1)&1] with next subkey.
// ---------------------------------------------------------------------------
__global__ __launch_bounds__(256) void k_sample(float* __restrict__ out, int t,
                                                uint32_t nsk0, uint32_t nsk1) {
  const int b = blockIdx.x;
  const int tid = threadIdx.x;
  const float* __restrict__ z   = &g_z[(size_t)b * VV];
  const float* __restrict__ gum = &g_gum[t & 1][(size_t)b * VV];

  float zv[8];
#pragma unroll
  for (int j = 0; j < 8; j++) zv[j] = z[tid + j * 256];

  __shared__ float red[256];
  __shared__ float rv[256];
  __shared__ int   ri[256];
  __shared__ int   s_sym;

  float m = zv[0];
#pragma unroll
  for (int j = 1; j < 8; j++) m = fmaxf(m, zv[j]);
  red[tid] = m; __syncthreads();
  for (int s = 128; s > 0; s >>= 1) {
    if (tid < s) red[tid] = fmaxf(red[tid], red[tid + s]);
    __syncthreads();
  }
  const float M = red[0]; __syncthreads();

  float ssum = 0.f;
#pragma unroll
  for (int j = 0; j < 8; j++) ssum += __expf(zv[j] - M);
  red[tid] = ssum; __syncthreads();
  for (int s = 128; s > 0; s >>= 1) {
    if (tid < s) red[tid] += red[tid + s];
    __syncthreads();
  }
  const float lse = logf(red[0]); __syncthreads();

  float entp = 0.f;
  float bestv = -INFINITY;
  int   besti = VV;
  const size_t probs_row = (size_t)PROBS_OFF + ((size_t)b * LP1 + t) * VV;
#pragma unroll
  for (int j = 0; j < 8; j++) {
    int v = tid + j * 256;
    float lsm = zv[j] - M - lse;
    float pr = __expf(lsm);
    out[probs_row + v] = pr;
    entp += pr * lsm;
    float val = gum[v] + lsm;
    if (val > bestv || (val == bestv && v < besti)) { bestv = val; besti = v; }
  }

  red[tid] = entp; __syncthreads();
  for (int s = 128; s > 0; s >>= 1) {
    if (tid < s) red[tid] += red[tid + s];
    __syncthreads();
  }
  const float ENT = red[0]; __syncthreads();

  rv[tid] = bestv; ri[tid] = besti; __syncthreads();
  for (int s = 128; s > 0; s >>= 1) {
    if (tid < s) {
      if (rv[tid + s] > rv[tid] ||
          (rv[tid + s] == rv[tid] && ri[tid + s] < ri[tid])) {
        rv[tid] = rv[tid + s]; ri[tid] = ri[tid + s];
      }
    }
    __syncthreads();
  }
  if (tid == 0) {
    int sym = ri[0];
    s_sym = sym;
    out[SEQ_OFF  + b * LP1 + t] = (float)sym;
    out[LOGP_OFF + b * LP1 + t] = z[sym] - M - lse;
    out[ENT_OFF  + b * LP1 + t] = -ENT;
  }
  __syncthreads();
  const int sym = s_sym;

  // LSTM(t+1): gates = P + EG[sym] + bg -> h planes for next step
  {
    const float* __restrict__ P = &g_P[(size_t)b * 2048];
    const float* __restrict__ eg = &g_EG[(size_t)sym * 2048];
    __half* Aout = &g_Ah[(t + 1) & 1][(size_t)b * 2048];
#pragma unroll
    for (int r = 0; r < 2; r++) {
      int hh = tid + r * 256;
      float hn = lstm_one(P, eg, b, hh);
      split4A(hn, &Aout[hh], 512);
    }
  }

  // hash next step's Gumbel field
  float* __restrict__ gd = &g_gum[(t + 1) & 1][0];
#pragma unroll
  for (int j = 0; j < 8; j++) {
    uint32_t idx = (uint32_t)(b * 2048 + tid + j * 256);
    gd[idx] = gumbel_of(nsk0, nsk1, idx);
  }
}

// ---------------------------------------------------------------------------
extern "C" void kernel_launch(void* const* d_in, const int* in_sizes, int n_in,
                              void* d_out, int out_size) {
  const float* x       = (const float*)d_in[0];
  const float* agent_w = (const float*)d_in[1];
  const float* agent_b = (const float*)d_in[2];
  const float* sos     = (const float*)d_in[3];
  const float* emb     = (const float*)d_in[4];
  const float* w_ih    = (const float*)d_in[5];
  const float* w_hh    = (const float*)d_in[6];
  const float* b_ih    = (const float*)d_in[7];
  const float* b_hh    = (const float*)d_in[8];
  const float* out_w   = (const float*)d_in[9];
  const float* out_b   = (const float*)d_in[10];
  float* out = (float*)d_out;

  cudaFuncSetAttribute(k_mgemm, cudaFuncAttributeMaxDynamicSharedMemorySize, SMEM_G);
  cudaFuncSetAttribute(k_eg,    cudaFuncAttributeMaxDynamicSharedMemorySize, SMEM_G);

  // per-step threefry subkeys (33: steps 0..31 + spare)
  uint32_t sk0[33], sk1[33];
  {
    uint32_t k0 = 0u, k1 = 1u;
    for (int t = 0; t < 33; t++) {
      uint32_t n0, n1, s0, s1;
      h_tf2x32(k0, k1, 0u, 0u, n0, n1);
      h_tf2x32(k0, k1, 0u, 1u, s0, s1);
      sk0[t] = s0; sk1[t] = s1; k0 = n0; k1 = n1;
    }
  }

  k_init<<<4096, 256>>>(b_ih, b_hh, out);                    // 1
  k_split_emb<<<4352, 256>>>(emb, sos);                      // 2
  k_split_wall<<<dim3(64, 16, 3), 256>>>(w_hh, w_ih, out_w); // 3
  k_eg<<<dim3(16, 17), 256, SMEM_G>>>();                     // 4
  k_h0<<<dim3(8, 8), 256>>>(x, agent_w, agent_b);            // 5 -> g_Ah[1]
  k_mgemm<<<dim3(32, 4), 256, SMEM_G>>>(1, out_b);           // 6 (profiled): P_0
  k_lstm0<<<512, 256>>>(sk0[0], sk1[0]);                     // 7 -> H_1, gum_0

  for (int t = 0; t < 32; t++) {
    k_mgemm<<<dim3(32, 4), 256, SMEM_G>>>(t & 1, out_b);     // z_t, P_{t+1}
    k_sample<<<512, 256>>>(out, t, sk0[t + 1], sk1[t + 1]);  // sym_t, LSTM, gum
  }
}